// round 1
// baseline (speedup 1.0000x reference)
#include <cuda_runtime.h>
#include <cuda_bf16.h>
#include <math.h>

// Problem constants (fixed by setup_inputs)
#define BB    4
#define TT    1024
#define CC    768
#define HH    12
#define DH    64
#define BT    4096            // B*T
#define C3    2304            // 3*C
#define C4    3072            // 4*C
#define ZSZ   3145728         // BT*C
#define NUM_ITERS 6

// ---------------- scratch (device globals; no allocation allowed) -----------
__device__ float g_z[ZSZ];
__device__ float g_x[ZSZ];            // LN outputs (reused)
__device__ float g_qkv[BT * C3];
__device__ float g_scores[(size_t)BB * HH * TT * TT];   // 192 MB
__device__ float g_attnout[ZSZ];
__device__ float g_zattn[ZSZ];
__device__ float g_mid[BT * C4];
__device__ float g_res[ZSZ];
__device__ float g_fhist[4 * ZSZ];    // circular residual history (Anderson)

// ---------------- generic tiled fp32 GEMM: out = A @ W^T + bias -------------
// A: [M,K] row-major, W: [N,K] row-major.
// MODE 0: +bias   MODE 1: gelu(+bias)   MODE 2: +bias+add1   MODE 3: +bias+add1-add2
template <int MODE>
__global__ void gemm_kernel(const float* __restrict__ A,
                            const float* __restrict__ W,
                            const float* __restrict__ bias,
                            float* __restrict__ out,
                            int M, int N, int K,
                            const float* __restrict__ add1,
                            const float* __restrict__ add2) {
    __shared__ float As[16][65];
    __shared__ float Bs[16][65];
    const int tid = threadIdx.x;
    const int bm = blockIdx.y * 64;
    const int bn = blockIdx.x * 64;
    const int lr = tid >> 2;            // 0..63  (row within tile for loads)
    const int lk = (tid & 3) << 2;      // 0,4,8,12
    const int tm0 = (tid >> 4) << 2;    // output micro-tile row base
    const int tn0 = (tid & 15) << 2;    // output micro-tile col base

    float acc[4][4] = {};
    const float* Arow = A + (size_t)(bm + lr) * K + lk;
    const float* Wrow = W + (size_t)(bn + lr) * K + lk;

    for (int k0 = 0; k0 < K; k0 += 16) {
        float4 av = *(const float4*)(Arow + k0);
        float4 wv = *(const float4*)(Wrow + k0);
        As[lk + 0][lr] = av.x; As[lk + 1][lr] = av.y;
        As[lk + 2][lr] = av.z; As[lk + 3][lr] = av.w;
        Bs[lk + 0][lr] = wv.x; Bs[lk + 1][lr] = wv.y;
        Bs[lk + 2][lr] = wv.z; Bs[lk + 3][lr] = wv.w;
        __syncthreads();
#pragma unroll
        for (int k = 0; k < 16; k++) {
            float a0 = As[k][tm0 + 0], a1 = As[k][tm0 + 1];
            float a2 = As[k][tm0 + 2], a3 = As[k][tm0 + 3];
            float b0 = Bs[k][tn0 + 0], b1 = Bs[k][tn0 + 1];
            float b2 = Bs[k][tn0 + 2], b3 = Bs[k][tn0 + 3];
            acc[0][0] += a0 * b0; acc[0][1] += a0 * b1; acc[0][2] += a0 * b2; acc[0][3] += a0 * b3;
            acc[1][0] += a1 * b0; acc[1][1] += a1 * b1; acc[1][2] += a1 * b2; acc[1][3] += a1 * b3;
            acc[2][0] += a2 * b0; acc[2][1] += a2 * b1; acc[2][2] += a2 * b2; acc[2][3] += a2 * b3;
            acc[3][0] += a3 * b0; acc[3][1] += a3 * b1; acc[3][2] += a3 * b2; acc[3][3] += a3 * b3;
        }
        __syncthreads();
    }

#pragma unroll
    for (int i = 0; i < 4; i++) {
        const int m = bm + tm0 + i;
#pragma unroll
        for (int j = 0; j < 4; j++) {
            const int n = bn + tn0 + j;
            float v = acc[i][j] + bias[n];
            if (MODE == 1) {
                v = 0.5f * v * (1.0f + erff(v * 0.70710678118654752f));
            }
            const size_t oidx = (size_t)m * N + n;
            if (MODE == 2) v += add1[oidx];
            if (MODE == 3) v += add1[oidx] - add2[oidx];
            out[oidx] = v;
        }
    }
}

// ---------------- fused add + LayerNorm (one block per token row) -----------
__global__ void ln_kernel(const float* __restrict__ zin,
                          const float* __restrict__ u,
                          const float* __restrict__ emb,
                          const float* __restrict__ w,
                          const float* __restrict__ b,
                          float* __restrict__ out) {
    __shared__ float red[256];
    const int row = blockIdx.x;
    const int tid = threadIdx.x;
    const size_t base = (size_t)row * CC;
    float v[3];
    float s = 0.0f;
#pragma unroll
    for (int i = 0; i < 3; i++) {
        const int c = tid + i * 256;
        float x = zin[base + c];
        if (u)   x += u[base + c];
        if (emb) x += 0.1f * emb[c];
        v[i] = x;
        s += x;
    }
    red[tid] = s; __syncthreads();
    for (int st = 128; st > 0; st >>= 1) {
        if (tid < st) red[tid] += red[tid + st];
        __syncthreads();
    }
    const float mu = red[0] * (1.0f / CC);
    __syncthreads();
    float s2 = 0.0f;
#pragma unroll
    for (int i = 0; i < 3; i++) { v[i] -= mu; s2 += v[i] * v[i]; }
    red[tid] = s2; __syncthreads();
    for (int st = 128; st > 0; st >>= 1) {
        if (tid < st) red[tid] += red[tid + st];
        __syncthreads();
    }
    const float rs = rsqrtf(red[0] * (1.0f / CC) + 1e-5f);
#pragma unroll
    for (int i = 0; i < 3; i++) {
        const int c = tid + i * 256;
        out[base + c] = v[i] * rs * w[c] + b[c];
    }
}

// ---------------- attention: scores = Q K^T / 8 ------------------------------
// grid: (T/64 key tiles, T/64 query tiles, B*H), block 256
__global__ void attn_scores_kernel(const float* __restrict__ qkv,
                                   float* __restrict__ scores) {
    __shared__ float Qs[64][65];
    __shared__ float Ks[64][65];
    const int tid = threadIdx.x;
    const int bh = blockIdx.z;
    const int b = bh / HH, h = bh % HH;
    const int tk0 = blockIdx.x * 64;
    const int tq0 = blockIdx.y * 64;
    const int tm0 = (tid >> 4) << 2;
    const int tn0 = (tid & 15) << 2;

#pragma unroll
    for (int i = 0; i < 4; i++) {
        const int idx = tid + i * 256;     // 0..1023
        const int r = idx >> 4;            // 0..63
        const int d4 = (idx & 15) << 2;    // 0..60
        float4 q = *(const float4*)(qkv + (size_t)(b * TT + tq0 + r) * C3 + h * DH + d4);
        float4 k = *(const float4*)(qkv + (size_t)(b * TT + tk0 + r) * C3 + CC + h * DH + d4);
        Qs[r][d4 + 0] = q.x; Qs[r][d4 + 1] = q.y; Qs[r][d4 + 2] = q.z; Qs[r][d4 + 3] = q.w;
        Ks[r][d4 + 0] = k.x; Ks[r][d4 + 1] = k.y; Ks[r][d4 + 2] = k.z; Ks[r][d4 + 3] = k.w;
    }
    __syncthreads();

    float acc[4][4] = {};
#pragma unroll 8
    for (int k = 0; k < 64; k++) {
        float a0 = Qs[tm0 + 0][k], a1 = Qs[tm0 + 1][k];
        float a2 = Qs[tm0 + 2][k], a3 = Qs[tm0 + 3][k];
        float b0 = Ks[tn0 + 0][k], b1 = Ks[tn0 + 1][k];
        float b2 = Ks[tn0 + 2][k], b3 = Ks[tn0 + 3][k];
        acc[0][0] += a0 * b0; acc[0][1] += a0 * b1; acc[0][2] += a0 * b2; acc[0][3] += a0 * b3;
        acc[1][0] += a1 * b0; acc[1][1] += a1 * b1; acc[1][2] += a1 * b2; acc[1][3] += a1 * b3;
        acc[2][0] += a2 * b0; acc[2][1] += a2 * b1; acc[2][2] += a2 * b2; acc[2][3] += a2 * b3;
        acc[3][0] += a3 * b0; acc[3][1] += a3 * b1; acc[3][2] += a3 * b2; acc[3][3] += a3 * b3;
    }

#pragma unroll
    for (int i = 0; i < 4; i++)
#pragma unroll
        for (int j = 0; j < 4; j++)
            scores[(size_t)(bh * TT + tq0 + tm0 + i) * TT + tk0 + tn0 + j] =
                acc[i][j] * 0.125f;   // 1/sqrt(64)
}

// ---------------- softmax over rows of length 1024 ---------------------------
__global__ void softmax_kernel(float* __restrict__ sc) {
    __shared__ float red[256];
    const int tid = threadIdx.x;
    const size_t base = (size_t)blockIdx.x * TT;
    float v[4];
    float m = -1e30f;
#pragma unroll
    for (int i = 0; i < 4; i++) { v[i] = sc[base + tid + i * 256]; m = fmaxf(m, v[i]); }
    red[tid] = m; __syncthreads();
    for (int st = 128; st > 0; st >>= 1) {
        if (tid < st) red[tid] = fmaxf(red[tid], red[tid + st]);
        __syncthreads();
    }
    m = red[0]; __syncthreads();
    float s = 0.0f;
#pragma unroll
    for (int i = 0; i < 4; i++) { v[i] = __expf(v[i] - m); s += v[i]; }
    red[tid] = s; __syncthreads();
    for (int st = 128; st > 0; st >>= 1) {
        if (tid < st) red[tid] += red[tid + st];
        __syncthreads();
    }
    const float inv = 1.0f / red[0];
#pragma unroll
    for (int i = 0; i < 4; i++) sc[base + tid + i * 256] = v[i] * inv;
}

// ---------------- attention: out = att @ V -----------------------------------
// grid: (T/64 query tiles, B*H), block 256
__global__ void attn_av_kernel(const float* __restrict__ scores,
                               const float* __restrict__ qkv,
                               float* __restrict__ attnout) {
    __shared__ float Ats[64][65];
    __shared__ float Vs[64][65];
    const int tid = threadIdx.x;
    const int bh = blockIdx.y;
    const int b = bh / HH, h = bh % HH;
    const int tq0 = blockIdx.x * 64;
    const int tm0 = (tid >> 4) << 2;
    const int tn0 = (tid & 15) << 2;

    float acc[4][4] = {};
    for (int jc = 0; jc < TT; jc += 64) {
#pragma unroll
        for (int i = 0; i < 4; i++) {
            const int idx = tid + i * 256;
            const int r = idx >> 4;
            const int d4 = (idx & 15) << 2;
            float4 a = *(const float4*)(scores + (size_t)(bh * TT + tq0 + r) * TT + jc + d4);
            float4 vv = *(const float4*)(qkv + (size_t)(b * TT + jc + r) * C3 + 2 * CC + h * DH + d4);
            Ats[r][d4 + 0] = a.x; Ats[r][d4 + 1] = a.y; Ats[r][d4 + 2] = a.z; Ats[r][d4 + 3] = a.w;
            Vs[r][d4 + 0] = vv.x; Vs[r][d4 + 1] = vv.y; Vs[r][d4 + 2] = vv.z; Vs[r][d4 + 3] = vv.w;
        }
        __syncthreads();
#pragma unroll 8
        for (int k = 0; k < 64; k++) {
            float a0 = Ats[tm0 + 0][k], a1 = Ats[tm0 + 1][k];
            float a2 = Ats[tm0 + 2][k], a3 = Ats[tm0 + 3][k];
            float b0 = Vs[k][tn0 + 0], b1 = Vs[k][tn0 + 1];
            float b2 = Vs[k][tn0 + 2], b3 = Vs[k][tn0 + 3];
            acc[0][0] += a0 * b0; acc[0][1] += a0 * b1; acc[0][2] += a0 * b2; acc[0][3] += a0 * b3;
            acc[1][0] += a1 * b0; acc[1][1] += a1 * b1; acc[1][2] += a1 * b2; acc[1][3] += a1 * b3;
            acc[2][0] += a2 * b0; acc[2][1] += a2 * b1; acc[2][2] += a2 * b2; acc[2][3] += a2 * b3;
            acc[3][0] += a3 * b0; acc[3][1] += a3 * b1; acc[3][2] += a3 * b2; acc[3][3] += a3 * b3;
        }
        __syncthreads();
    }

#pragma unroll
    for (int i = 0; i < 4; i++)
#pragma unroll
        for (int j = 0; j < 4; j++)
            attnout[(size_t)(b * TT + tq0 + tm0 + i) * CC + h * DH + tn0 + j] = acc[i][j];
}

// ---------------- Anderson acceleration update (one block per token) ---------
// K = min(it,4) previous residuals live in fhist slots (it-K+j)%4.
// Solves (dF dF^T + 1e-6 I) alpha = dF r ; z += r - dF^T alpha ; stores r at slot it%4.
__global__ void anderson_kernel(float* __restrict__ z,
                                const float* __restrict__ res,
                                float* __restrict__ fh, int it) {
    __shared__ float sh[14][256];
    __shared__ float alpha_sh[4];
    const int n = blockIdx.x, tid = threadIdx.x;
    const size_t base = (size_t)n * CC;
    const int K = it < 4 ? it : 4;
    const int c0 = tid, c1 = tid + 256, c2 = tid + 512;

    float r0 = res[base + c0], r1 = res[base + c1], r2 = res[base + c2];
    float dF[4][3];
    for (int j = 0; j < K; j++) {
        const int slot = (it - K + j) & 3;
        const float* f = fh + (size_t)slot * ZSZ + base;
        dF[j][0] = f[c0] - r0; dF[j][1] = f[c1] - r1; dF[j][2] = f[c2] - r2;
    }

    if (K > 0) {
        int idx = 0;
        for (int k = 0; k < K; k++)
            for (int l = k; l < K; l++) {
                sh[idx][tid] = dF[k][0] * dF[l][0] + dF[k][1] * dF[l][1] + dF[k][2] * dF[l][2];
                idx++;
            }
        for (int k = 0; k < K; k++) {
            sh[idx][tid] = dF[k][0] * r0 + dF[k][1] * r1 + dF[k][2] * r2;
            idx++;
        }
        const int np = idx;
        __syncthreads();
        for (int st = 128; st > 0; st >>= 1) {
            if (tid < st)
                for (int v = 0; v < np; v++) sh[v][tid] += sh[v][tid + st];
            __syncthreads();
        }
        if (tid == 0) {
            float G[4][4], bv[4], al[4];
            int id2 = 0;
            for (int k = 0; k < K; k++)
                for (int l = k; l < K; l++) { G[k][l] = G[l][k] = sh[id2][0]; id2++; }
            for (int k = 0; k < K; k++) { G[k][k] += 1e-6f; bv[k] = sh[id2][0]; id2++; }
            for (int p = 0; p < K; p++) {
                const float inv = 1.0f / G[p][p];
                for (int rr = p + 1; rr < K; rr++) {
                    const float f2 = G[rr][p] * inv;
                    for (int cc = p; cc < K; cc++) G[rr][cc] -= f2 * G[p][cc];
                    bv[rr] -= f2 * bv[p];
                }
            }
            for (int p = K - 1; p >= 0; p--) {
                float s = bv[p];
                for (int cc = p + 1; cc < K; cc++) s -= G[p][cc] * al[cc];
                al[p] = s / G[p][p];
            }
            for (int k = 0; k < K; k++) alpha_sh[k] = al[k];
        }
        __syncthreads();
        float d0 = r0, d1 = r1, d2 = r2;
        for (int j = 0; j < K; j++) {
            const float a = alpha_sh[j];
            d0 -= a * dF[j][0]; d1 -= a * dF[j][1]; d2 -= a * dF[j][2];
        }
        z[base + c0] += d0; z[base + c1] += d1; z[base + c2] += d2;
    } else {
        z[base + c0] += r0; z[base + c1] += r1; z[base + c2] += r2;
    }

    float* fs = fh + (size_t)(it & 3) * ZSZ + base;
    fs[c0] = r0; fs[c1] = r1; fs[c2] = r2;
}

// ---------------- host launcher ----------------------------------------------
static float* symaddr(const void* s) {
    void* p = nullptr;
    cudaGetSymbolAddress(&p, s);
    return (float*)p;
}

extern "C" void kernel_launch(void* const* d_in, const int* in_sizes, int n_in,
                              void* d_out, int out_size) {
    const float* u          = (const float*)d_in[0];
    const float* iter_emb   = (const float*)d_in[1];
    const float* ln1_w      = (const float*)d_in[2];
    const float* ln1_b      = (const float*)d_in[3];
    const float* in_proj_w  = (const float*)d_in[4];
    const float* in_proj_b  = (const float*)d_in[5];
    const float* out_proj_w = (const float*)d_in[6];
    const float* out_proj_b = (const float*)d_in[7];
    const float* ln2_w      = (const float*)d_in[8];
    const float* ln2_b      = (const float*)d_in[9];
    const float* mlp_w1     = (const float*)d_in[10];
    const float* mlp_b1     = (const float*)d_in[11];
    const float* mlp_w2     = (const float*)d_in[12];
    const float* mlp_b2     = (const float*)d_in[13];
    // d_in[14] = num_iters (device scalar, fixed to 6 by the problem; cannot be
    // read synchronously under graph capture)

    float* zp   = symaddr(g_z);
    float* xp   = symaddr(g_x);
    float* qkvp = symaddr(g_qkv);
    float* scp  = symaddr(g_scores);
    float* aop  = symaddr(g_attnout);
    float* zap  = symaddr(g_zattn);
    float* midp = symaddr(g_mid);
    float* resp = symaddr(g_res);
    float* fhp  = symaddr(g_fhist);

    cudaMemsetAsync(zp, 0, (size_t)ZSZ * sizeof(float), 0);

    for (int it = 0; it < NUM_ITERS; it++) {
        // x = LN1(z + 0.1*emb[it] + u)
        ln_kernel<<<BT, 256>>>(zp, u, iter_emb + it * CC, ln1_w, ln1_b, xp);
        // qkv = x @ Wqkv^T + b
        gemm_kernel<0><<<dim3(C3 / 64, BT / 64), 256>>>(xp, in_proj_w, in_proj_b,
                                                        qkvp, BT, C3, CC, nullptr, nullptr);
        // scores = Q K^T / sqrt(dh)
        attn_scores_kernel<<<dim3(TT / 64, TT / 64, BB * HH), 256>>>(qkvp, scp);
        softmax_kernel<<<BB * HH * TT, 256>>>(scp);
        attn_av_kernel<<<dim3(TT / 64, BB * HH), 256>>>(scp, qkvp, aop);
        // z_attn = z + attnout @ Wo^T + bo
        gemm_kernel<2><<<dim3(CC / 64, BT / 64), 256>>>(aop, out_proj_w, out_proj_b,
                                                        zap, BT, CC, CC, zp, nullptr);
        // h = LN2(z_attn)
        ln_kernel<<<BT, 256>>>(zap, nullptr, nullptr, ln2_w, ln2_b, xp);
        // mid = gelu(h @ W1^T + b1)
        gemm_kernel<1><<<dim3(C4 / 64, BT / 64), 256>>>(xp, mlp_w1, mlp_b1,
                                                        midp, BT, C4, CC, nullptr, nullptr);
        // res = (mid @ W2^T + b2) + z_attn - z
        gemm_kernel<3><<<dim3(CC / 64, BT / 64), 256>>>(midp, mlp_w2, mlp_b2,
                                                        resp, BT, CC, C4, zap, zp);
        // Anderson update of z, residual history push
        anderson_kernel<<<BT, 256>>>(zp, resp, fhp, it);
    }

    cudaMemcpyAsync(d_out, zp, (size_t)ZSZ * sizeof(float),
                    cudaMemcpyDeviceToDevice, 0);
}

// round 3
// speedup vs baseline: 1.6266x; 1.6266x over previous
#include <cuda_runtime.h>
#include <cuda_bf16.h>
#include <math.h>

// Problem constants (fixed by setup_inputs)
#define BB    4
#define TT    1024
#define CC    768
#define HH    12
#define DH    64
#define BT    4096            // B*T
#define C3    2304            // 3*C
#define C4    3072            // 4*C
#define ZSZ   3145728         // BT*C
#define NUM_ITERS 6

// ---------------- scratch (device globals; no allocation allowed) -----------
__device__ float g_z[ZSZ];
__device__ float g_x[ZSZ];            // LN outputs (reused)
__device__ float g_qkv[BT * C3];
__device__ float g_scores[(size_t)BB * HH * TT * TT];   // 192 MB
__device__ float g_attnout[ZSZ];
__device__ float g_zattn[ZSZ];
__device__ float g_mid[BT * C4];
__device__ float g_res[ZSZ];
__device__ float g_fhist[4 * ZSZ];    // circular residual history (Anderson)

// ---------------- tf32 helpers ----------------------------------------------
__device__ __forceinline__ unsigned f2tf(float x) {
    unsigned u;
    asm("cvt.rna.tf32.f32 %0, %1;" : "=r"(u) : "f"(x));
    return u;
}

__device__ __forceinline__ void mma8(float c[4], const unsigned a[4], const unsigned b[2]) {
    asm volatile(
        "mma.sync.aligned.m16n8k8.row.col.f32.tf32.tf32.f32 "
        "{%0,%1,%2,%3}, {%4,%5,%6,%7}, {%8,%9}, {%0,%1,%2,%3};\n"
        : "+f"(c[0]), "+f"(c[1]), "+f"(c[2]), "+f"(c[3])
        : "r"(a[0]), "r"(a[1]), "r"(a[2]), "r"(a[3]), "r"(b[0]), "r"(b[1]));
}

// ---------------- unified tensor-core GEMM ------------------------------------
// out[m,n] = sum_k A[m,k] * B[n,k]   (B "k-major"), or B[k,n] when BTRANS.
// Tile: 128(M) x 64(N) x 16(K), 256 threads = 8 warps (4x2), warp tile 32x32.
// All launches use the tf32x3 split (hi*hi + hi*lo + lo*hi): ~fp32 accuracy.
// MODE: 0 +bias | 1 gelu(+bias) | 2 +bias+add1 | 3 +bias+add1-add2 | 4 *0.125 | 5 none
// Batch (blockIdx.z): offsets b*SB + h*SH applied to A, B, out (z = b*HH + h).
template<int MODE, bool BTRANS>
__global__ void __launch_bounds__(256) mma_gemm(
    const float* __restrict__ A, const float* __restrict__ Bm,
    const float* __restrict__ bias, float* __restrict__ out,
    int K, int lda, int ldb, int ldc,
    long aSB, long aSH, long bSB, long bSH, long oSB, long oSH,
    const float* __restrict__ add1, const float* __restrict__ add2)
{
    __shared__ float As[2][128][20];
    __shared__ float Bs[2][64][20];

    {
        const int z = blockIdx.z;
        const int b = z / HH, h = z % HH;
        A   += (size_t)b * aSB + (size_t)h * aSH;
        Bm  += (size_t)b * bSB + (size_t)h * bSH;
        out += (size_t)b * oSB + (size_t)h * oSH;
    }
    const int tid  = threadIdx.x;
    const int lane = tid & 31;
    const int wid  = tid >> 5;
    const int wm   = wid >> 1;     // 0..3
    const int wn   = wid & 1;      // 0..1
    const int m0   = blockIdx.y * 128;
    const int n0   = blockIdx.x * 64;

    const int arow = tid >> 2;          // 0..63
    const int acol = (tid & 3) << 2;    // 0,4,8,12
    const int tkrow = tid >> 4;         // 0..15  (BTRANS loader)
    const int tncol = (tid & 15) << 2;  // 0..60

    const int nsteps = K >> 4;

    // prologue: load k-step 0
    float4 pa0 = *(const float4*)(A + (size_t)(m0 + arow) * lda + acol);
    float4 pa1 = *(const float4*)(A + (size_t)(m0 + arow + 64) * lda + acol);
    float4 pb;
    if (!BTRANS) pb = *(const float4*)(Bm + (size_t)(n0 + arow) * ldb + acol);
    else         pb = *(const float4*)(Bm + (size_t)tkrow * ldb + n0 + tncol);

    *(float4*)&As[0][arow][acol]      = pa0;
    *(float4*)&As[0][arow + 64][acol] = pa1;
    if (!BTRANS) {
        *(float4*)&Bs[0][arow][acol] = pb;
    } else {
        Bs[0][tncol + 0][tkrow] = pb.x; Bs[0][tncol + 1][tkrow] = pb.y;
        Bs[0][tncol + 2][tkrow] = pb.z; Bs[0][tncol + 3][tkrow] = pb.w;
    }
    __syncthreads();

    float acc[2][4][4];
#pragma unroll
    for (int i = 0; i < 2; i++)
#pragma unroll
        for (int j = 0; j < 4; j++)
#pragma unroll
            for (int e = 0; e < 4; e++) acc[i][j][e] = 0.0f;

    for (int s = 0; s < nsteps; s++) {
        const int cur = s & 1;
        if (s + 1 < nsteps) {
            const int kg = (s + 1) << 4;
            pa0 = *(const float4*)(A + (size_t)(m0 + arow) * lda + kg + acol);
            pa1 = *(const float4*)(A + (size_t)(m0 + arow + 64) * lda + kg + acol);
            if (!BTRANS) pb = *(const float4*)(Bm + (size_t)(n0 + arow) * ldb + kg + acol);
            else         pb = *(const float4*)(Bm + (size_t)(kg + tkrow) * ldb + n0 + tncol);
        }

#pragma unroll
        for (int ks = 0; ks < 16; ks += 8) {
            unsigned ahi[2][4], alo[2][4];
#pragma unroll
            for (int mt = 0; mt < 2; mt++) {
                const int r0 = wm * 32 + mt * 16 + (lane >> 2);
                const int c0 = ks + (lane & 3);
                float x0 = As[cur][r0][c0];
                float x1 = As[cur][r0 + 8][c0];
                float x2 = As[cur][r0][c0 + 4];
                float x3 = As[cur][r0 + 8][c0 + 4];
                ahi[mt][0] = f2tf(x0); ahi[mt][1] = f2tf(x1);
                ahi[mt][2] = f2tf(x2); ahi[mt][3] = f2tf(x3);
                alo[mt][0] = f2tf(x0 - __uint_as_float(ahi[mt][0]));
                alo[mt][1] = f2tf(x1 - __uint_as_float(ahi[mt][1]));
                alo[mt][2] = f2tf(x2 - __uint_as_float(ahi[mt][2]));
                alo[mt][3] = f2tf(x3 - __uint_as_float(ahi[mt][3]));
            }
            unsigned bhi[4][2], blo[4][2];
#pragma unroll
            for (int nt = 0; nt < 4; nt++) {
                const int nb = wn * 32 + nt * 8 + (lane >> 2);
                const int kk = ks + (lane & 3);
                float y0 = Bs[cur][nb][kk];
                float y1 = Bs[cur][nb][kk + 4];
                bhi[nt][0] = f2tf(y0); bhi[nt][1] = f2tf(y1);
                blo[nt][0] = f2tf(y0 - __uint_as_float(bhi[nt][0]));
                blo[nt][1] = f2tf(y1 - __uint_as_float(bhi[nt][1]));
            }
#pragma unroll
            for (int mt = 0; mt < 2; mt++)
#pragma unroll
                for (int nt = 0; nt < 4; nt++) {
                    mma8(acc[mt][nt], ahi[mt], blo[nt]);
                    mma8(acc[mt][nt], alo[mt], bhi[nt]);
                    mma8(acc[mt][nt], ahi[mt], bhi[nt]);
                }
        }

        if (s + 1 < nsteps) {
            const int nb = cur ^ 1;
            *(float4*)&As[nb][arow][acol]      = pa0;
            *(float4*)&As[nb][arow + 64][acol] = pa1;
            if (!BTRANS) {
                *(float4*)&Bs[nb][arow][acol] = pb;
            } else {
                Bs[nb][tncol + 0][tkrow] = pb.x; Bs[nb][tncol + 1][tkrow] = pb.y;
                Bs[nb][tncol + 2][tkrow] = pb.z; Bs[nb][tncol + 3][tkrow] = pb.w;
            }
            __syncthreads();
        }
    }

    // epilogue
#pragma unroll
    for (int mt = 0; mt < 2; mt++) {
#pragma unroll
        for (int nt = 0; nt < 4; nt++) {
            const int r = m0 + wm * 32 + mt * 16 + (lane >> 2);
            const int c = n0 + wn * 32 + nt * 8 + 2 * (lane & 3);
#pragma unroll
            for (int e = 0; e < 4; e++) {
                const int rr = r + (e >> 1) * 8;
                const int cc = c + (e & 1);
                float v = acc[mt][nt][e];
                if (MODE <= 3) v += bias[cc];
                if (MODE == 1) v = 0.5f * v * (1.0f + erff(v * 0.70710678118654752f));
                const size_t oidx = (size_t)rr * ldc + cc;
                if (MODE == 2) v += add1[oidx];
                if (MODE == 3) v += add1[oidx] - add2[oidx];
                if (MODE == 4) v *= 0.125f;
                out[oidx] = v;
            }
        }
    }
}

// ---------------- fused add + LayerNorm (one block per token row) -----------
__global__ void ln_kernel(const float* __restrict__ zin,
                          const float* __restrict__ u,
                          const float* __restrict__ emb,
                          const float* __restrict__ w,
                          const float* __restrict__ b,
                          float* __restrict__ out) {
    __shared__ float red[256];
    const int row = blockIdx.x;
    const int tid = threadIdx.x;
    const size_t base = (size_t)row * CC;
    float v[3];
    float s = 0.0f;
#pragma unroll
    for (int i = 0; i < 3; i++) {
        const int c = tid + i * 256;
        float x = zin[base + c];
        if (u)   x += u[base + c];
        if (emb) x += 0.1f * emb[c];
        v[i] = x;
        s += x;
    }
    red[tid] = s; __syncthreads();
    for (int st = 128; st > 0; st >>= 1) {
        if (tid < st) red[tid] += red[tid + st];
        __syncthreads();
    }
    const float mu = red[0] * (1.0f / CC);
    __syncthreads();
    float s2 = 0.0f;
#pragma unroll
    for (int i = 0; i < 3; i++) { v[i] -= mu; s2 += v[i] * v[i]; }
    red[tid] = s2; __syncthreads();
    for (int st = 128; st > 0; st >>= 1) {
        if (tid < st) red[tid] += red[tid + st];
        __syncthreads();
    }
    const float rs = rsqrtf(red[0] * (1.0f / CC) + 1e-5f);
#pragma unroll
    for (int i = 0; i < 3; i++) {
        const int c = tid + i * 256;
        out[base + c] = v[i] * rs * w[c] + b[c];
    }
}

// ---------------- softmax over rows of length 1024 ---------------------------
__global__ void softmax_kernel(float* __restrict__ sc) {
    __shared__ float red[256];
    const int tid = threadIdx.x;
    const size_t base = (size_t)blockIdx.x * TT;
    float v[4];
    float m = -1e30f;
#pragma unroll
    for (int i = 0; i < 4; i++) { v[i] = sc[base + tid + i * 256]; m = fmaxf(m, v[i]); }
    red[tid] = m; __syncthreads();
    for (int st = 128; st > 0; st >>= 1) {
        if (tid < st) red[tid] = fmaxf(red[tid], red[tid + st]);
        __syncthreads();
    }
    m = red[0]; __syncthreads();
    float s = 0.0f;
#pragma unroll
    for (int i = 0; i < 4; i++) { v[i] = __expf(v[i] - m); s += v[i]; }
    red[tid] = s; __syncthreads();
    for (int st = 128; st > 0; st >>= 1) {
        if (tid < st) red[tid] += red[tid + st];
        __syncthreads();
    }
    const float inv = 1.0f / red[0];
#pragma unroll
    for (int i = 0; i < 4; i++) sc[base + tid + i * 256] = v[i] * inv;
}

// ---------------- Anderson acceleration update (one block per token) ---------
__global__ void anderson_kernel(float* __restrict__ z,
                                const float* __restrict__ res,
                                float* __restrict__ fh, int it) {
    __shared__ float sh[14][256];
    __shared__ float alpha_sh[4];
    const int n = blockIdx.x, tid = threadIdx.x;
    const size_t base = (size_t)n * CC;
    const int K = it < 4 ? it : 4;
    const int c0 = tid, c1 = tid + 256, c2 = tid + 512;

    float r0 = res[base + c0], r1 = res[base + c1], r2 = res[base + c2];
    float dF[4][3];
    for (int j = 0; j < K; j++) {
        const int slot = (it - K + j) & 3;
        const float* f = fh + (size_t)slot * ZSZ + base;
        dF[j][0] = f[c0] - r0; dF[j][1] = f[c1] - r1; dF[j][2] = f[c2] - r2;
    }

    if (K > 0) {
        int idx = 0;
        for (int k = 0; k < K; k++)
            for (int l = k; l < K; l++) {
                sh[idx][tid] = dF[k][0] * dF[l][0] + dF[k][1] * dF[l][1] + dF[k][2] * dF[l][2];
                idx++;
            }
        for (int k = 0; k < K; k++) {
            sh[idx][tid] = dF[k][0] * r0 + dF[k][1] * r1 + dF[k][2] * r2;
            idx++;
        }
        const int np = idx;
        __syncthreads();
        for (int st = 128; st > 0; st >>= 1) {
            if (tid < st)
                for (int v = 0; v < np; v++) sh[v][tid] += sh[v][tid + st];
            __syncthreads();
        }
        if (tid == 0) {
            float G[4][4], bv[4], al[4];
            int id2 = 0;
            for (int k = 0; k < K; k++)
                for (int l = k; l < K; l++) { G[k][l] = G[l][k] = sh[id2][0]; id2++; }
            for (int k = 0; k < K; k++) { G[k][k] += 1e-6f; bv[k] = sh[id2][0]; id2++; }
            for (int p = 0; p < K; p++) {
                const float inv = 1.0f / G[p][p];
                for (int rr = p + 1; rr < K; rr++) {
                    const float f2 = G[rr][p] * inv;
                    for (int cc = p; cc < K; cc++) G[rr][cc] -= f2 * G[p][cc];
                    bv[rr] -= f2 * bv[p];
                }
            }
            for (int p = K - 1; p >= 0; p--) {
                float s = bv[p];
                for (int cc = p + 1; cc < K; cc++) s -= G[p][cc] * al[cc];
                al[p] = s / G[p][p];
            }
            for (int k = 0; k < K; k++) alpha_sh[k] = al[k];
        }
        __syncthreads();
        float d0 = r0, d1 = r1, d2 = r2;
        for (int j = 0; j < K; j++) {
            const float a = alpha_sh[j];
            d0 -= a * dF[j][0]; d1 -= a * dF[j][1]; d2 -= a * dF[j][2];
        }
        z[base + c0] += d0; z[base + c1] += d1; z[base + c2] += d2;
    } else {
        z[base + c0] += r0; z[base + c1] += r1; z[base + c2] += r2;
    }

    float* fs = fh + (size_t)(it & 3) * ZSZ + base;
    fs[c0] = r0; fs[c1] = r1; fs[c2] = r2;
}

// ---------------- host launcher ----------------------------------------------
static float* symaddr(const void* s) {
    void* p = nullptr;
    cudaGetSymbolAddress(&p, s);
    return (float*)p;
}

extern "C" void kernel_launch(void* const* d_in, const int* in_sizes, int n_in,
                              void* d_out, int out_size) {
    const float* u          = (const float*)d_in[0];
    const float* iter_emb   = (const float*)d_in[1];
    const float* ln1_w      = (const float*)d_in[2];
    const float* ln1_b      = (const float*)d_in[3];
    const float* in_proj_w  = (const float*)d_in[4];
    const float* in_proj_b  = (const float*)d_in[5];
    const float* out_proj_w = (const float*)d_in[6];
    const float* out_proj_b = (const float*)d_in[7];
    const float* ln2_w      = (const float*)d_in[8];
    const float* ln2_b      = (const float*)d_in[9];
    const float* mlp_w1     = (const float*)d_in[10];
    const float* mlp_b1     = (const float*)d_in[11];
    const float* mlp_w2     = (const float*)d_in[12];
    const float* mlp_b2     = (const float*)d_in[13];
    // d_in[14] = num_iters (fixed to 6 by setup_inputs)

    float* zp   = symaddr(g_z);
    float* xp   = symaddr(g_x);
    float* qkvp = symaddr(g_qkv);
    float* scp  = symaddr(g_scores);
    float* aop  = symaddr(g_attnout);
    float* zap  = symaddr(g_zattn);
    float* midp = symaddr(g_mid);
    float* resp = symaddr(g_res);
    float* fhp  = symaddr(g_fhist);

    cudaMemsetAsync(zp, 0, (size_t)ZSZ * sizeof(float), 0);

    for (int it = 0; it < NUM_ITERS; it++) {
        // x = LN1(z + 0.1*emb[it] + u)
        ln_kernel<<<BT, 256>>>(zp, u, iter_emb + it * CC, ln1_w, ln1_b, xp);

        // qkv = x @ Wqkv^T + b
        mma_gemm<0, false><<<dim3(C3 / 64, BT / 128, 1), 256>>>(
            xp, in_proj_w, in_proj_b, qkvp, CC, CC, CC, C3,
            0, 0, 0, 0, 0, 0, nullptr, nullptr);

        // scores = Q K^T / 8   (batched over B*H)
        mma_gemm<4, false><<<dim3(TT / 64, TT / 128, BB * HH), 256>>>(
            qkvp, qkvp + CC, nullptr, scp, DH, C3, C3, TT,
            (long)TT * C3, 64, (long)TT * C3, 64,
            (long)HH * TT * TT, (long)TT * TT, nullptr, nullptr);

        softmax_kernel<<<BB * HH * TT, 256>>>(scp);

        // attnout = att @ V   (V staged transposed)
        mma_gemm<5, true><<<dim3(1, TT / 128, BB * HH), 256>>>(
            scp, qkvp + 2 * CC, nullptr, aop, TT, TT, C3, CC,
            (long)HH * TT * TT, (long)TT * TT, (long)TT * C3, 64,
            (long)TT * CC, 64, nullptr, nullptr);

        // z_attn = z + attnout @ Wo^T + bo
        mma_gemm<2, false><<<dim3(CC / 64, BT / 128, 1), 256>>>(
            aop, out_proj_w, out_proj_b, zap, CC, CC, CC, CC,
            0, 0, 0, 0, 0, 0, zp, nullptr);

        // h = LN2(z_attn)
        ln_kernel<<<BT, 256>>>(zap, nullptr, nullptr, ln2_w, ln2_b, xp);

        // mid = gelu(h @ W1^T + b1)
        mma_gemm<1, false><<<dim3(C4 / 64, BT / 128, 1), 256>>>(
            xp, mlp_w1, mlp_b1, midp, CC, CC, CC, C4,
            0, 0, 0, 0, 0, 0, nullptr, nullptr);

        // res = (mid @ W2^T + b2) + z_attn - z
        mma_gemm<3, false><<<dim3(CC / 64, BT / 128, 1), 256>>>(
            midp, mlp_w2, mlp_b2, resp, C4, C4, C4, CC,
            0, 0, 0, 0, 0, 0, zap, zp);

        // Anderson update of z, residual history push
        anderson_kernel<<<BT, 256>>>(zp, resp, fhp, it);
    }

    cudaMemcpyAsync(d_out, zp, (size_t)ZSZ * sizeof(float),
                    cudaMemcpyDeviceToDevice, 0);
}

// round 5
// speedup vs baseline: 2.0128x; 1.2375x over previous
#include <cuda_runtime.h>
#include <cuda_bf16.h>
#include <math.h>
#include <stdint.h>

// Problem constants (fixed by setup_inputs)
#define BB    4
#define TT    1024
#define CC    768
#define HH    12
#define DH    64
#define BT    4096            // B*T
#define C3    2304            // 3*C
#define C4    3072            // 4*C
#define ZSZ   3145728         // BT*C
#define NUM_ITERS 6

// ---------------- scratch (device globals; no allocation allowed) -----------
__device__ float g_z[ZSZ];
__device__ float g_x[ZSZ];
__device__ float g_qkv[BT * C3];
__device__ float g_scores[(size_t)BB * HH * TT * TT];   // 192 MB
__device__ float g_attnout[ZSZ];
__device__ float g_zattn[ZSZ];
__device__ float g_mid[BT * C4];
__device__ float g_res[ZSZ];
__device__ float g_fhist[4 * ZSZ];

// ---------------- bf16 split helpers -----------------------------------------
// x = hi + lo with hi = bf16(x), lo = bf16(x - hi); pack pairs along k.
__device__ __forceinline__ void split2(float x, float y, uint32_t& hi, uint32_t& lo) {
    __nv_bfloat162 h2 = __floats2bfloat162_rn(x, y);
    float lx = x - __low2float(h2);
    float ly = y - __high2float(h2);
    __nv_bfloat162 l2 = __floats2bfloat162_rn(lx, ly);
    hi = *reinterpret_cast<uint32_t*>(&h2);
    lo = *reinterpret_cast<uint32_t*>(&l2);
}

__device__ __forceinline__ void mma16(float c[4], const uint32_t a[4], const uint32_t b[2]) {
    asm volatile(
        "mma.sync.aligned.m16n8k16.row.col.f32.bf16.bf16.f32 "
        "{%0,%1,%2,%3}, {%4,%5,%6,%7}, {%8,%9}, {%0,%1,%2,%3};\n"
        : "+f"(c[0]), "+f"(c[1]), "+f"(c[2]), "+f"(c[3])
        : "r"(a[0]), "r"(a[1]), "r"(a[2]), "r"(a[3]), "r"(b[0]), "r"(b[1]));
}

// ---------------- unified tensor-core GEMM (bf16x3) ---------------------------
// out[m,n] = sum_k A[m,k] * B[n,k]   (B k-major), or B[k,n] when BTRANS.
// Tile: 128(M) x 64(N) x 16(K), 256 threads = 8 warps (4x2), warp tile 32x32.
// hi/lo bf16 tiles staged in smem (packed bf16x2 along k, fragment order);
// 3 MMA passes: hi*lo + lo*hi + hi*hi  => ~2^-18 per-product accuracy.
// MODE: 0 +bias | 1 gelu(+bias) | 2 +bias+add1 | 3 +bias+add1-add2 | 4 *0.125 | 5 none
template<int MODE, bool BTRANS>
__global__ void __launch_bounds__(256) mma_gemm(
    const float* __restrict__ A, const float* __restrict__ Bm,
    const float* __restrict__ bias, float* __restrict__ out,
    int K, int lda, int ldb, int ldc,
    long aSB, long aSH, long bSB, long bSH, long oSB, long oSH,
    const float* __restrict__ add1, const float* __restrict__ add2)
{
    // [buf][row][kp] : kp = packed pair of k (bf16x2). 9-word row pad vs banks.
    __shared__ uint32_t Ah[2][128][9], Al[2][128][9];
    __shared__ uint32_t Bh[2][64][9],  Bl[2][64][9];

    {
        const int z = blockIdx.z;
        const int b = z / HH, h = z % HH;
        A   += (size_t)b * aSB + (size_t)h * aSH;
        Bm  += (size_t)b * bSB + (size_t)h * bSH;
        out += (size_t)b * oSB + (size_t)h * oSH;
    }
    const int tid  = threadIdx.x;
    const int lane = tid & 31;
    const int wid  = tid >> 5;
    const int wm   = wid >> 1;     // 0..3
    const int wn   = wid & 1;      // 0..1
    const int m0   = blockIdx.y * 128;
    const int n0   = blockIdx.x * 64;

    const int nsteps = K >> 4;

    // ---- loader lambdas ------------------------------------------------------
    auto load_a = [&](int s, float4 pa[2]) {
#pragma unroll
        for (int i = 0; i < 2; i++) {
            const int idx = tid + i * 256;          // 0..511
            const int row = idx >> 2;               // 0..127
            const int kq  = (idx & 3) << 2;         // 0,4,8,12
            pa[i] = *(const float4*)(A + (size_t)(m0 + row) * lda + (s << 4) + kq);
        }
    };
    auto store_a = [&](int buf, const float4 pa[2]) {
#pragma unroll
        for (int i = 0; i < 2; i++) {
            const int idx = tid + i * 256;
            const int row = idx >> 2;
            const int kp  = (idx & 3) << 1;         // 0,2,4,6
            uint32_t h0, l0, h1, l1;
            split2(pa[i].x, pa[i].y, h0, l0);
            split2(pa[i].z, pa[i].w, h1, l1);
            Ah[buf][row][kp]     = h0; Ah[buf][row][kp + 1] = h1;
            Al[buf][row][kp]     = l0; Al[buf][row][kp + 1] = l1;
        }
    };
    auto load_b = [&](int s, float4& pb, float pbt[4]) {
        if (!BTRANS) {
            const int row = tid >> 2;               // 0..63
            const int kq  = (tid & 3) << 2;
            pb = *(const float4*)(Bm + (size_t)(n0 + row) * ldb + (s << 4) + kq);
        } else {
#pragma unroll
            for (int i = 0; i < 2; i++) {
                const int idx = tid + i * 256;      // 0..511
                const int kp  = idx >> 6;           // 0..7
                const int n   = idx & 63;
                pbt[i * 2 + 0] = Bm[(size_t)((s << 4) + 2 * kp)     * ldb + n0 + n];
                pbt[i * 2 + 1] = Bm[(size_t)((s << 4) + 2 * kp + 1) * ldb + n0 + n];
            }
        }
    };
    auto store_b = [&](int buf, const float4& pb, const float pbt[4]) {
        if (!BTRANS) {
            const int row = tid >> 2;
            const int kp  = (tid & 3) << 1;
            uint32_t h0, l0, h1, l1;
            split2(pb.x, pb.y, h0, l0);
            split2(pb.z, pb.w, h1, l1);
            Bh[buf][row][kp]     = h0; Bh[buf][row][kp + 1] = h1;
            Bl[buf][row][kp]     = l0; Bl[buf][row][kp + 1] = l1;
        } else {
#pragma unroll
            for (int i = 0; i < 2; i++) {
                const int idx = tid + i * 256;
                const int kp  = idx >> 6;
                const int n   = idx & 63;
                uint32_t h0, l0;
                split2(pbt[i * 2 + 0], pbt[i * 2 + 1], h0, l0);
                Bh[buf][n][kp] = h0;
                Bl[buf][n][kp] = l0;
            }
        }
    };

    // ---- prologue: k-step 0 --------------------------------------------------
    float4 pa[2], pb;
    float  pbt[4];
    load_a(0, pa);
    load_b(0, pb, pbt);
    store_a(0, pa);
    store_b(0, pb, pbt);
    __syncthreads();

    float acc[2][4][4];
#pragma unroll
    for (int i = 0; i < 2; i++)
#pragma unroll
        for (int j = 0; j < 4; j++)
#pragma unroll
            for (int e = 0; e < 4; e++) acc[i][j][e] = 0.0f;

    const int kp = lane & 3;
    const int qr = lane >> 2;

    for (int s = 0; s < nsteps; s++) {
        const int cur = s & 1;
        if (s + 1 < nsteps) {
            load_a(s + 1, pa);
            load_b(s + 1, pb, pbt);
        }

        uint32_t ah[2][4], al4[2][4];
#pragma unroll
        for (int mt = 0; mt < 2; mt++) {
            const int r0 = wm * 32 + mt * 16 + qr;
            ah[mt][0] = Ah[cur][r0][kp];      ah[mt][1] = Ah[cur][r0 + 8][kp];
            ah[mt][2] = Ah[cur][r0][kp + 4];  ah[mt][3] = Ah[cur][r0 + 8][kp + 4];
            al4[mt][0] = Al[cur][r0][kp];     al4[mt][1] = Al[cur][r0 + 8][kp];
            al4[mt][2] = Al[cur][r0][kp + 4]; al4[mt][3] = Al[cur][r0 + 8][kp + 4];
        }
        uint32_t bh2[4][2], bl2[4][2];
#pragma unroll
        for (int nt = 0; nt < 4; nt++) {
            const int n = wn * 32 + nt * 8 + qr;
            bh2[nt][0] = Bh[cur][n][kp]; bh2[nt][1] = Bh[cur][n][kp + 4];
            bl2[nt][0] = Bl[cur][n][kp]; bl2[nt][1] = Bl[cur][n][kp + 4];
        }
#pragma unroll
        for (int mt = 0; mt < 2; mt++)
#pragma unroll
            for (int nt = 0; nt < 4; nt++) {
                mma16(acc[mt][nt], ah[mt],  bl2[nt]);
                mma16(acc[mt][nt], al4[mt], bh2[nt]);
                mma16(acc[mt][nt], ah[mt],  bh2[nt]);
            }

        if (s + 1 < nsteps) {
            const int nb = cur ^ 1;
            store_a(nb, pa);
            store_b(nb, pb, pbt);
            __syncthreads();
        }
    }

    // ---- epilogue --------------------------------------------------------------
#pragma unroll
    for (int mt = 0; mt < 2; mt++) {
#pragma unroll
        for (int nt = 0; nt < 4; nt++) {
            const int r = m0 + wm * 32 + mt * 16 + qr;
            const int c = n0 + wn * 32 + nt * 8 + 2 * kp;
#pragma unroll
            for (int e = 0; e < 4; e++) {
                const int rr = r + (e >> 1) * 8;
                const int cc = c + (e & 1);
                float v = acc[mt][nt][e];
                if (MODE <= 3) v += bias[cc];
                if (MODE == 1) v = 0.5f * v * (1.0f + erff(v * 0.70710678118654752f));
                const size_t oidx = (size_t)rr * ldc + cc;
                if (MODE == 2) v += add1[oidx];
                if (MODE == 3) v += add1[oidx] - add2[oidx];
                if (MODE == 4) v *= 0.125f;
                out[oidx] = v;
            }
        }
    }
}

// ---------------- fused add + LayerNorm --------------------------------------
__global__ void ln_kernel(const float* __restrict__ zin,
                          const float* __restrict__ u,
                          const float* __restrict__ emb,
                          const float* __restrict__ w,
                          const float* __restrict__ b,
                          float* __restrict__ out) {
    __shared__ float red[256];
    const int row = blockIdx.x;
    const int tid = threadIdx.x;
    const size_t base = (size_t)row * CC;
    float v[3];
    float s = 0.0f;
#pragma unroll
    for (int i = 0; i < 3; i++) {
        const int c = tid + i * 256;
        float x = zin[base + c];
        if (u)   x += u[base + c];
        if (emb) x += 0.1f * emb[c];
        v[i] = x;
        s += x;
    }
    red[tid] = s; __syncthreads();
    for (int st = 128; st > 0; st >>= 1) {
        if (tid < st) red[tid] += red[tid + st];
        __syncthreads();
    }
    const float mu = red[0] * (1.0f / CC);
    __syncthreads();
    float s2 = 0.0f;
#pragma unroll
    for (int i = 0; i < 3; i++) { v[i] -= mu; s2 += v[i] * v[i]; }
    red[tid] = s2; __syncthreads();
    for (int st = 128; st > 0; st >>= 1) {
        if (tid < st) red[tid] += red[tid + st];
        __syncthreads();
    }
    const float rs = rsqrtf(red[0] * (1.0f / CC) + 1e-5f);
#pragma unroll
    for (int i = 0; i < 3; i++) {
        const int c = tid + i * 256;
        out[base + c] = v[i] * rs * w[c] + b[c];
    }
}

// ---------------- softmax over rows of length 1024 ---------------------------
__global__ void softmax_kernel(float* __restrict__ sc) {
    __shared__ float red[256];
    const int tid = threadIdx.x;
    const size_t base = (size_t)blockIdx.x * TT;
    float v[4];
    float m = -1e30f;
#pragma unroll
    for (int i = 0; i < 4; i++) { v[i] = sc[base + tid + i * 256]; m = fmaxf(m, v[i]); }
    red[tid] = m; __syncthreads();
    for (int st = 128; st > 0; st >>= 1) {
        if (tid < st) red[tid] = fmaxf(red[tid], red[tid + st]);
        __syncthreads();
    }
    m = red[0]; __syncthreads();
    float s = 0.0f;
#pragma unroll
    for (int i = 0; i < 4; i++) { v[i] = __expf(v[i] - m); s += v[i]; }
    red[tid] = s; __syncthreads();
    for (int st = 128; st > 0; st >>= 1) {
        if (tid < st) red[tid] += red[tid + st];
        __syncthreads();
    }
    const float inv = 1.0f / red[0];
#pragma unroll
    for (int i = 0; i < 4; i++) sc[base + tid + i * 256] = v[i] * inv;
}

// ---------------- Anderson acceleration update (one block per token) ---------
__global__ void anderson_kernel(float* __restrict__ z,
                                const float* __restrict__ res,
                                float* __restrict__ fh, int it) {
    __shared__ float sh[14][256];
    __shared__ float alpha_sh[4];
    const int n = blockIdx.x, tid = threadIdx.x;
    const size_t base = (size_t)n * CC;
    const int K = it < 4 ? it : 4;
    const int c0 = tid, c1 = tid + 256, c2 = tid + 512;

    float r0 = res[base + c0], r1 = res[base + c1], r2 = res[base + c2];
    float dF[4][3];
    for (int j = 0; j < K; j++) {
        const int slot = (it - K + j) & 3;
        const float* f = fh + (size_t)slot * ZSZ + base;
        dF[j][0] = f[c0] - r0; dF[j][1] = f[c1] - r1; dF[j][2] = f[c2] - r2;
    }

    if (K > 0) {
        int idx = 0;
        for (int k = 0; k < K; k++)
            for (int l = k; l < K; l++) {
                sh[idx][tid] = dF[k][0] * dF[l][0] + dF[k][1] * dF[l][1] + dF[k][2] * dF[l][2];
                idx++;
            }
        for (int k = 0; k < K; k++) {
            sh[idx][tid] = dF[k][0] * r0 + dF[k][1] * r1 + dF[k][2] * r2;
            idx++;
        }
        const int np = idx;
        __syncthreads();
        for (int st = 128; st > 0; st >>= 1) {
            if (tid < st)
                for (int v = 0; v < np; v++) sh[v][tid] += sh[v][tid + st];
            __syncthreads();
        }
        if (tid == 0) {
            float G[4][4], bv[4], al[4];
            int id2 = 0;
            for (int k = 0; k < K; k++)
                for (int l = k; l < K; l++) { G[k][l] = G[l][k] = sh[id2][0]; id2++; }
            for (int k = 0; k < K; k++) { G[k][k] += 1e-6f; bv[k] = sh[id2][0]; id2++; }
            for (int p = 0; p < K; p++) {
                const float inv = 1.0f / G[p][p];
                for (int rr = p + 1; rr < K; rr++) {
                    const float f2 = G[rr][p] * inv;
                    for (int cc = p; cc < K; cc++) G[rr][cc] -= f2 * G[p][cc];
                    bv[rr] -= f2 * bv[p];
                }
            }
            for (int p = K - 1; p >= 0; p--) {
                float s = bv[p];
                for (int cc = p + 1; cc < K; cc++) s -= G[p][cc] * al[cc];
                al[p] = s / G[p][p];
            }
            for (int k = 0; k < K; k++) alpha_sh[k] = al[k];
        }
        __syncthreads();
        float d0 = r0, d1 = r1, d2 = r2;
        for (int j = 0; j < K; j++) {
            const float a = alpha_sh[j];
            d0 -= a * dF[j][0]; d1 -= a * dF[j][1]; d2 -= a * dF[j][2];
        }
        z[base + c0] += d0; z[base + c1] += d1; z[base + c2] += d2;
    } else {
        z[base + c0] += r0; z[base + c1] += r1; z[base + c2] += r2;
    }

    float* fs = fh + (size_t)(it & 3) * ZSZ + base;
    fs[c0] = r0; fs[c1] = r1; fs[c2] = r2;
}

// ---------------- host launcher ----------------------------------------------
static float* symaddr(const void* s) {
    void* p = nullptr;
    cudaGetSymbolAddress(&p, s);
    return (float*)p;
}

extern "C" void kernel_launch(void* const* d_in, const int* in_sizes, int n_in,
                              void* d_out, int out_size) {
    const float* u          = (const float*)d_in[0];
    const float* iter_emb   = (const float*)d_in[1];
    const float* ln1_w      = (const float*)d_in[2];
    const float* ln1_b      = (const float*)d_in[3];
    const float* in_proj_w  = (const float*)d_in[4];
    const float* in_proj_b  = (const float*)d_in[5];
    const float* out_proj_w = (const float*)d_in[6];
    const float* out_proj_b = (const float*)d_in[7];
    const float* ln2_w      = (const float*)d_in[8];
    const float* ln2_b      = (const float*)d_in[9];
    const float* mlp_w1     = (const float*)d_in[10];
    const float* mlp_b1     = (const float*)d_in[11];
    const float* mlp_w2     = (const float*)d_in[12];
    const float* mlp_b2     = (const float*)d_in[13];
    // d_in[14] = num_iters (fixed to 6 by setup_inputs)

    float* zp   = symaddr(g_z);
    float* xp   = symaddr(g_x);
    float* qkvp = symaddr(g_qkv);
    float* scp  = symaddr(g_scores);
    float* aop  = symaddr(g_attnout);
    float* zap  = symaddr(g_zattn);
    float* midp = symaddr(g_mid);
    float* resp = symaddr(g_res);
    float* fhp  = symaddr(g_fhist);

    cudaMemsetAsync(zp, 0, (size_t)ZSZ * sizeof(float), 0);

    for (int it = 0; it < NUM_ITERS; it++) {
        // x = LN1(z + 0.1*emb[it] + u)
        ln_kernel<<<BT, 256>>>(zp, u, iter_emb + it * CC, ln1_w, ln1_b, xp);

        // qkv = x @ Wqkv^T + b
        mma_gemm<0, false><<<dim3(C3 / 64, BT / 128, 1), 256>>>(
            xp, in_proj_w, in_proj_b, qkvp, CC, CC, CC, C3,
            0, 0, 0, 0, 0, 0, nullptr, nullptr);

        // scores = Q K^T / 8   (batched over B*H)
        mma_gemm<4, false><<<dim3(TT / 64, TT / 128, BB * HH), 256>>>(
            qkvp, qkvp + CC, nullptr, scp, DH, C3, C3, TT,
            (long)TT * C3, 64, (long)TT * C3, 64,
            (long)HH * TT * TT, (long)TT * TT, nullptr, nullptr);

        softmax_kernel<<<BB * HH * TT, 256>>>(scp);

        // attnout = att @ V   (V transposed at stage time)
        mma_gemm<5, true><<<dim3(1, TT / 128, BB * HH), 256>>>(
            scp, qkvp + 2 * CC, nullptr, aop, TT, TT, C3, CC,
            (long)HH * TT * TT, (long)TT * TT, (long)TT * C3, 64,
            (long)TT * CC, 64, nullptr, nullptr);

        // z_attn = z + attnout @ Wo^T + bo
        mma_gemm<2, false><<<dim3(CC / 64, BT / 128, 1), 256>>>(
            aop, out_proj_w, out_proj_b, zap, CC, CC, CC, CC,
            0, 0, 0, 0, 0, 0, zp, nullptr);

        // h = LN2(z_attn)
        ln_kernel<<<BT, 256>>>(zap, nullptr, nullptr, ln2_w, ln2_b, xp);

        // mid = gelu(h @ W1^T + b1)
        mma_gemm<1, false><<<dim3(C4 / 64, BT / 128, 1), 256>>>(
            xp, mlp_w1, mlp_b1, midp, CC, CC, CC, C4,
            0, 0, 0, 0, 0, 0, nullptr, nullptr);

        // res = (mid @ W2^T + b2) + z_attn - z
        mma_gemm<3, false><<<dim3(CC / 64, BT / 128, 1), 256>>>(
            midp, mlp_w2, mlp_b2, resp, C4, C4, C4, CC,
            0, 0, 0, 0, 0, 0, zap, zp);

        // Anderson update of z, residual history push
        anderson_kernel<<<BT, 256>>>(zp, resp, fhp, it);
    }

    cudaMemcpyAsync(d_out, zp, (size_t)ZSZ * sizeof(float),
                    cudaMemcpyDeviceToDevice, 0);
}

// round 6
// speedup vs baseline: 2.0380x; 1.0125x over previous
#include <cuda_runtime.h>
#include <cuda_bf16.h>
#include <math.h>
#include <stdint.h>

// Problem constants (fixed by setup_inputs)
#define BB    4
#define TT    1024
#define CC    768
#define HH    12
#define DH    64
#define BT    4096            // B*T
#define C3    2304            // 3*C
#define C4    3072            // 4*C
#define ZSZ   3145728         // BT*C
#define NUM_ITERS 6
// pair (bf16x2) leading dims
#define CCP   384
#define C3P   1152
#define C4P   1536
#define TTP   512
#define DHP   32

// ---------------- scratch (device globals; no allocation allowed) -----------
__device__ float g_z[ZSZ];
__device__ float g_zattn[ZSZ];
__device__ float g_res[ZSZ];
__device__ float g_fhist[4 * ZSZ];
__device__ float g_scores[(size_t)BB * HH * TT * TT];      // fp32 logits (192MB)

// hi/lo bf16x2 planes (pairs packed along k)
__device__ uint32_t g_x_h[BT * CCP],    g_x_l[BT * CCP];      // LN out (x and h)
__device__ uint32_t g_qkv_h[BT * C3P],  g_qkv_l[BT * C3P];
__device__ uint32_t g_sc_h[(size_t)BB * HH * TT * TTP];
__device__ uint32_t g_sc_l[(size_t)BB * HH * TT * TTP];
__device__ uint32_t g_ao_h[BT * CCP],   g_ao_l[BT * CCP];
__device__ uint32_t g_mid_h[BT * C4P],  g_mid_l[BT * C4P];
// weight planes (split once per launch)
__device__ uint32_t g_wqkv_h[C3 * CCP], g_wqkv_l[C3 * CCP];
__device__ uint32_t g_wo_h[CC * CCP],   g_wo_l[CC * CCP];
__device__ uint32_t g_w1_h[C4 * CCP],   g_w1_l[C4 * CCP];
__device__ uint32_t g_w2_h[CC * C4P],   g_w2_l[CC * C4P];

// ---------------- bf16 split helpers -----------------------------------------
__device__ __forceinline__ void split2(float x, float y, uint32_t& hi, uint32_t& lo) {
    __nv_bfloat162 h2 = __floats2bfloat162_rn(x, y);
    float lx = x - __low2float(h2);
    float ly = y - __high2float(h2);
    __nv_bfloat162 l2 = __floats2bfloat162_rn(lx, ly);
    hi = *reinterpret_cast<uint32_t*>(&h2);
    lo = *reinterpret_cast<uint32_t*>(&l2);
}

__device__ __forceinline__ void mma16(float c[4], const uint32_t a[4], const uint32_t b[2]) {
    asm volatile(
        "mma.sync.aligned.m16n8k16.row.col.f32.bf16.bf16.f32 "
        "{%0,%1,%2,%3}, {%4,%5,%6,%7}, {%8,%9}, {%0,%1,%2,%3};\n"
        : "+f"(c[0]), "+f"(c[1]), "+f"(c[2]), "+f"(c[3])
        : "r"(a[0]), "r"(a[1]), "r"(a[2]), "r"(a[3]), "r"(b[0]), "r"(b[1]));
}

// ---------------- weight/activation split kernel ------------------------------
__global__ void conv_kernel(const float* __restrict__ w,
                            uint32_t* __restrict__ h,
                            uint32_t* __restrict__ l, int npairs) {
    int i = blockIdx.x * 256 + threadIdx.x;
    if (i < npairs) {
        float2 x = ((const float2*)w)[i];
        uint32_t hv, lv;
        split2(x.x, x.y, hv, lv);
        h[i] = hv; l[i] = lv;
    }
}

// ---------------- unified tensor-core GEMM (bf16x3, pre-split planes) ---------
// out[m,n] = sum_k A[m,k] * B[n,k]   (planes pre-split, pairs packed along k).
// BTRANS (AV): B = V read from qkv planes [token][channel-pair], repacked to
//              [channel][token-pair] with byte_perm (no float math).
// Tile: 128(M) x 64(N) x 16(K), 256 threads = 8 warps (4x2), warp tile 32x32.
// 3 MMA passes: hi*lo + lo*hi + hi*hi.
// MODE: 0 +bias | 1 gelu(+bias) | 2 +bias+add1 | 3 +bias+add1-add2 | 4 *0.125 | 5 none
// OUTP: write hi/lo planes (pairs along n) instead of fp32.
template<int MODE, bool BTRANS, bool OUTP>
__global__ void __launch_bounds__(256) mma_gemm(
    const uint32_t* __restrict__ Agh, const uint32_t* __restrict__ Agl,
    const uint32_t* __restrict__ Bgh, const uint32_t* __restrict__ Bgl,
    const float* __restrict__ bias,
    float* __restrict__ outF, uint32_t* __restrict__ outH, uint32_t* __restrict__ outL,
    int K, int ldaP, int ldbP, int ldc,
    long aSB, long aSH, long bSB, long bSH, long oSB, long oSH,
    const float* __restrict__ add1, const float* __restrict__ add2)
{
    __shared__ uint32_t sAh[2][128][12], sAl[2][128][12];
    __shared__ uint32_t sBh[2][64][12],  sBl[2][64][12];

    {
        const int z = blockIdx.z;
        const int b = z / HH, h = z % HH;
        Agh += (size_t)b * aSB + (size_t)h * aSH;
        Agl += (size_t)b * aSB + (size_t)h * aSH;
        Bgh += (size_t)b * bSB + (size_t)h * bSH;
        Bgl += (size_t)b * bSB + (size_t)h * bSH;
        const size_t oo = (size_t)b * oSB + (size_t)h * oSH;
        if (OUTP) { outH += oo; outL += oo; }
        else      { outF += oo; }
        if (add1) add1 += oo;
        if (add2) add2 += oo;
    }
    const int tid  = threadIdx.x;
    const int lane = tid & 31;
    const int wid  = tid >> 5;
    const int wm   = wid >> 1;     // 0..3
    const int wn   = wid & 1;      // 0..1
    const int m0   = blockIdx.y * 128;
    const int n0   = blockIdx.x * 64;

    const int nsteps = K >> 4;     // k-steps of 16 elems = 8 pairs

    const int arow = tid >> 1;          // 0..127
    const int akq  = (tid & 1) << 2;    // 0 or 4 (pair units)

    // ---- loaders ---------------------------------------------------------------
    uint4 pah, pal, pbh, pbl;                 // A always, B non-trans (tid<128)
    uint32_t vth[4], vtl[4];                  // BTRANS repacked outputs (2 per i)

    auto load_a = [&](int s) {
        const size_t off = (size_t)(m0 + arow) * ldaP + (s << 3) + akq;
        pah = *(const uint4*)(Agh + off);
        pal = *(const uint4*)(Agl + off);
    };
    auto store_a = [&](int buf) {
        *(uint4*)&sAh[buf][arow][akq] = pah;
        *(uint4*)&sAl[buf][arow][akq] = pal;
    };
    auto load_b = [&](int s) {
        if (!BTRANS) {
            if (tid < 128) {
                const int brow = tid >> 1;
                const size_t off = (size_t)(n0 + brow) * ldbP + (s << 3) + akq;
                pbh = *(const uint4*)(Bgh + off);
                pbl = *(const uint4*)(Bgl + off);
            }
        } else {
#pragma unroll
            for (int i = 0; i < 2; i++) {
                const int idx = tid + i * 256;
                const int n  = idx & 63;             // channel within tile
                const int kp = idx >> 6;             // token pair 0..7
                const size_t r0 = (size_t)((s << 4) + 2 * kp) * ldbP + ((n0 + n) >> 1);
                const uint32_t sel = (n & 1) ? 0x7632u : 0x5410u;
                uint32_t w0 = Bgh[r0],        w1 = Bgh[r0 + ldbP];
                vth[i] = __byte_perm(w0, w1, sel);
                w0 = Bgl[r0]; w1 = Bgl[r0 + ldbP];
                vtl[i] = __byte_perm(w0, w1, sel);
            }
        }
    };
    auto store_b = [&](int buf) {
        if (!BTRANS) {
            if (tid < 128) {
                const int brow = tid >> 1;
                *(uint4*)&sBh[buf][brow][akq] = pbh;
                *(uint4*)&sBl[buf][brow][akq] = pbl;
            }
        } else {
#pragma unroll
            for (int i = 0; i < 2; i++) {
                const int idx = tid + i * 256;
                const int n  = idx & 63;
                const int kp = idx >> 6;
                sBh[buf][n][kp] = vth[i];
                sBl[buf][n][kp] = vtl[i];
            }
        }
    };

    // ---- prologue ---------------------------------------------------------------
    load_a(0); load_b(0);
    store_a(0); store_b(0);
    __syncthreads();

    float acc[2][4][4];
#pragma unroll
    for (int i = 0; i < 2; i++)
#pragma unroll
        for (int j = 0; j < 4; j++)
#pragma unroll
            for (int e = 0; e < 4; e++) acc[i][j][e] = 0.0f;

    const int kp = lane & 3;
    const int qr = lane >> 2;

    for (int s = 0; s < nsteps; s++) {
        const int cur = s & 1;
        if (s + 1 < nsteps) { load_a(s + 1); load_b(s + 1); }

        uint32_t ah[2][4], al4[2][4];
#pragma unroll
        for (int mt = 0; mt < 2; mt++) {
            const int r0 = wm * 32 + mt * 16 + qr;
            ah[mt][0] = sAh[cur][r0][kp];      ah[mt][1] = sAh[cur][r0 + 8][kp];
            ah[mt][2] = sAh[cur][r0][kp + 4];  ah[mt][3] = sAh[cur][r0 + 8][kp + 4];
            al4[mt][0] = sAl[cur][r0][kp];     al4[mt][1] = sAl[cur][r0 + 8][kp];
            al4[mt][2] = sAl[cur][r0][kp + 4]; al4[mt][3] = sAl[cur][r0 + 8][kp + 4];
        }
        uint32_t bh2[4][2], bl2[4][2];
#pragma unroll
        for (int nt = 0; nt < 4; nt++) {
            const int n = wn * 32 + nt * 8 + qr;
            bh2[nt][0] = sBh[cur][n][kp]; bh2[nt][1] = sBh[cur][n][kp + 4];
            bl2[nt][0] = sBl[cur][n][kp]; bl2[nt][1] = sBl[cur][n][kp + 4];
        }
#pragma unroll
        for (int mt = 0; mt < 2; mt++)
#pragma unroll
            for (int nt = 0; nt < 4; nt++) {
                mma16(acc[mt][nt], ah[mt],  bl2[nt]);
                mma16(acc[mt][nt], al4[mt], bh2[nt]);
                mma16(acc[mt][nt], ah[mt],  bh2[nt]);
            }

        if (s + 1 < nsteps) {
            const int nb = cur ^ 1;
            store_a(nb); store_b(nb);
            __syncthreads();
        }
    }

    // ---- epilogue -----------------------------------------------------------------
#pragma unroll
    for (int mt = 0; mt < 2; mt++) {
#pragma unroll
        for (int nt = 0; nt < 4; nt++) {
            const int r = m0 + wm * 32 + mt * 16 + qr;
            const int c = n0 + wn * 32 + nt * 8 + 2 * kp;
            float vv[4];
#pragma unroll
            for (int e = 0; e < 4; e++) {
                const int cc = c + (e & 1);
                float v = acc[mt][nt][e];
                if (MODE <= 3) v += bias[cc];
                if (MODE == 1) v = 0.5f * v * (1.0f + erff(v * 0.70710678118654752f));
                if (MODE == 4) v *= 0.125f;
                vv[e] = v;
            }
            if (OUTP) {
                const int cp = c >> 1;
                uint32_t h0, l0, h1, l1;
                split2(vv[0], vv[1], h0, l0);
                split2(vv[2], vv[3], h1, l1);
                outH[(size_t)r * ldc + cp] = h0;       // ldc in pairs here
                outL[(size_t)r * ldc + cp] = l0;
                outH[(size_t)(r + 8) * ldc + cp] = h1;
                outL[(size_t)(r + 8) * ldc + cp] = l1;
            } else {
#pragma unroll
                for (int e = 0; e < 4; e++) {
                    const int rr = r + (e >> 1) * 8;
                    const int cc = c + (e & 1);
                    const size_t oidx = (size_t)rr * ldc + cc;
                    float v = vv[e];
                    if (MODE == 2) v += add1[oidx];
                    if (MODE == 3) v += add1[oidx] - add2[oidx];
                    outF[oidx] = v;
                }
            }
        }
    }
}

// ---------------- fused add + LayerNorm -> hi/lo planes -----------------------
__global__ void ln_kernel(const float* __restrict__ zin,
                          const float* __restrict__ u,
                          const float* __restrict__ emb,
                          const float* __restrict__ w,
                          const float* __restrict__ b,
                          uint32_t* __restrict__ oh,
                          uint32_t* __restrict__ ol) {
    __shared__ float red[256];
    const int row = blockIdx.x;
    const int tid = threadIdx.x;
    const size_t base = (size_t)row * CC;
    const float2* z2 = (const float2*)(zin + base);
    const float2* u2 = u ? (const float2*)(u + base) : nullptr;
    const float2* e2 = emb ? (const float2*)emb : nullptr;

    float2 va = z2[tid];
    float2 vb = make_float2(0.f, 0.f);
    if (u2) { float2 t = u2[tid]; va.x += t.x; va.y += t.y; }
    if (e2) { float2 t = e2[tid]; va.x += 0.1f * t.x; va.y += 0.1f * t.y; }
    if (tid < 128) {
        vb = z2[256 + tid];
        if (u2) { float2 t = u2[256 + tid]; vb.x += t.x; vb.y += t.y; }
        if (e2) { float2 t = e2[256 + tid]; vb.x += 0.1f * t.x; vb.y += 0.1f * t.y; }
    }
    float s = va.x + va.y + vb.x + vb.y;
    red[tid] = s; __syncthreads();
    for (int st = 128; st > 0; st >>= 1) {
        if (tid < st) red[tid] += red[tid + st];
        __syncthreads();
    }
    const float mu = red[0] * (1.0f / CC);
    __syncthreads();
    va.x -= mu; va.y -= mu;
    float s2 = va.x * va.x + va.y * va.y;
    if (tid < 128) { vb.x -= mu; vb.y -= mu; s2 += vb.x * vb.x + vb.y * vb.y; }
    red[tid] = s2; __syncthreads();
    for (int st = 128; st > 0; st >>= 1) {
        if (tid < st) red[tid] += red[tid + st];
        __syncthreads();
    }
    const float rs = rsqrtf(red[0] * (1.0f / CC) + 1e-5f);

    const float2* w2 = (const float2*)w;
    const float2* b2 = (const float2*)b;
    {
        float2 wc = w2[tid], bc = b2[tid];
        float y0 = va.x * rs * wc.x + bc.x;
        float y1 = va.y * rs * wc.y + bc.y;
        uint32_t hv, lv;
        split2(y0, y1, hv, lv);
        oh[(size_t)row * CCP + tid] = hv;
        ol[(size_t)row * CCP + tid] = lv;
    }
    if (tid < 128) {
        float2 wc = w2[256 + tid], bc = b2[256 + tid];
        float y0 = vb.x * rs * wc.x + bc.x;
        float y1 = vb.y * rs * wc.y + bc.y;
        uint32_t hv, lv;
        split2(y0, y1, hv, lv);
        oh[(size_t)row * CCP + 256 + tid] = hv;
        ol[(size_t)row * CCP + 256 + tid] = lv;
    }
}

// ---------------- softmax (fp32 in) -> hi/lo planes ---------------------------
__global__ void softmax_kernel(const float* __restrict__ sc,
                               uint32_t* __restrict__ oh,
                               uint32_t* __restrict__ ol) {
    __shared__ float red[256];
    const int tid = threadIdx.x;
    const size_t base = (size_t)blockIdx.x * TT;
    float4 v = ((const float4*)(sc + base))[tid];      // cols 4t..4t+3
    float m = fmaxf(fmaxf(v.x, v.y), fmaxf(v.z, v.w));
    red[tid] = m; __syncthreads();
    for (int st = 128; st > 0; st >>= 1) {
        if (tid < st) red[tid] = fmaxf(red[tid], red[tid + st]);
        __syncthreads();
    }
    m = red[0]; __syncthreads();
    v.x = __expf(v.x - m); v.y = __expf(v.y - m);
    v.z = __expf(v.z - m); v.w = __expf(v.w - m);
    red[tid] = v.x + v.y + v.z + v.w; __syncthreads();
    for (int st = 128; st > 0; st >>= 1) {
        if (tid < st) red[tid] += red[tid + st];
        __syncthreads();
    }
    const float inv = 1.0f / red[0];
    v.x *= inv; v.y *= inv; v.z *= inv; v.w *= inv;
    uint32_t h0, l0, h1, l1;
    split2(v.x, v.y, h0, l0);
    split2(v.z, v.w, h1, l1);
    const size_t pbase = (size_t)blockIdx.x * TTP;
    ((uint2*)(oh + pbase))[tid] = make_uint2(h0, h1);
    ((uint2*)(ol + pbase))[tid] = make_uint2(l0, l1);
}

// ---------------- Anderson acceleration update (one block per token) ---------
__global__ void anderson_kernel(float* __restrict__ z,
                                const float* __restrict__ res,
                                float* __restrict__ fh, int it) {
    __shared__ float sh[14][256];
    __shared__ float alpha_sh[4];
    const int n = blockIdx.x, tid = threadIdx.x;
    const size_t base = (size_t)n * CC;
    const int K = it < 4 ? it : 4;
    const int c0 = tid, c1 = tid + 256, c2 = tid + 512;

    float r0 = res[base + c0], r1 = res[base + c1], r2 = res[base + c2];
    float dF[4][3];
    for (int j = 0; j < K; j++) {
        const int slot = (it - K + j) & 3;
        const float* f = fh + (size_t)slot * ZSZ + base;
        dF[j][0] = f[c0] - r0; dF[j][1] = f[c1] - r1; dF[j][2] = f[c2] - r2;
    }

    if (K > 0) {
        int idx = 0;
        for (int k = 0; k < K; k++)
            for (int l = k; l < K; l++) {
                sh[idx][tid] = dF[k][0] * dF[l][0] + dF[k][1] * dF[l][1] + dF[k][2] * dF[l][2];
                idx++;
            }
        for (int k = 0; k < K; k++) {
            sh[idx][tid] = dF[k][0] * r0 + dF[k][1] * r1 + dF[k][2] * r2;
            idx++;
        }
        const int np = idx;
        __syncthreads();
        for (int st = 128; st > 0; st >>= 1) {
            if (tid < st)
                for (int v = 0; v < np; v++) sh[v][tid] += sh[v][tid + st];
            __syncthreads();
        }
        if (tid == 0) {
            float G[4][4], bv[4], al[4];
            int id2 = 0;
            for (int k = 0; k < K; k++)
                for (int l = k; l < K; l++) { G[k][l] = G[l][k] = sh[id2][0]; id2++; }
            for (int k = 0; k < K; k++) { G[k][k] += 1e-6f; bv[k] = sh[id2][0]; id2++; }
            for (int p = 0; p < K; p++) {
                const float inv = 1.0f / G[p][p];
                for (int rr = p + 1; rr < K; rr++) {
                    const float f2 = G[rr][p] * inv;
                    for (int cc = p; cc < K; cc++) G[rr][cc] -= f2 * G[p][cc];
                    bv[rr] -= f2 * bv[p];
                }
            }
            for (int p = K - 1; p >= 0; p--) {
                float s = bv[p];
                for (int cc = p + 1; cc < K; cc++) s -= G[p][cc] * al[cc];
                al[p] = s / G[p][p];
            }
            for (int k = 0; k < K; k++) alpha_sh[k] = al[k];
        }
        __syncthreads();
        float d0 = r0, d1 = r1, d2 = r2;
        for (int j = 0; j < K; j++) {
            const float a = alpha_sh[j];
            d0 -= a * dF[j][0]; d1 -= a * dF[j][1]; d2 -= a * dF[j][2];
        }
        z[base + c0] += d0; z[base + c1] += d1; z[base + c2] += d2;
    } else {
        z[base + c0] += r0; z[base + c1] += r1; z[base + c2] += r2;
    }

    float* fs = fh + (size_t)(it & 3) * ZSZ + base;
    fs[c0] = r0; fs[c1] = r1; fs[c2] = r2;
}

// ---------------- host launcher ----------------------------------------------
template <typename T>
static T* symaddr(const void* s) {
    void* p = nullptr;
    cudaGetSymbolAddress(&p, s);
    return (T*)p;
}

extern "C" void kernel_launch(void* const* d_in, const int* in_sizes, int n_in,
                              void* d_out, int out_size) {
    const float* u          = (const float*)d_in[0];
    const float* iter_emb   = (const float*)d_in[1];
    const float* ln1_w      = (const float*)d_in[2];
    const float* ln1_b      = (const float*)d_in[3];
    const float* in_proj_w  = (const float*)d_in[4];
    const float* in_proj_b  = (const float*)d_in[5];
    const float* out_proj_w = (const float*)d_in[6];
    const float* out_proj_b = (const float*)d_in[7];
    const float* ln2_w      = (const float*)d_in[8];
    const float* ln2_b      = (const float*)d_in[9];
    const float* mlp_w1     = (const float*)d_in[10];
    const float* mlp_b1     = (const float*)d_in[11];
    const float* mlp_w2     = (const float*)d_in[12];
    const float* mlp_b2     = (const float*)d_in[13];
    // d_in[14] = num_iters (fixed to 6 by setup_inputs)

    float* zp   = symaddr<float>(g_z);
    float* zap  = symaddr<float>(g_zattn);
    float* resp = symaddr<float>(g_res);
    float* fhp  = symaddr<float>(g_fhist);
    float* scp  = symaddr<float>(g_scores);
    uint32_t* xh   = symaddr<uint32_t>(g_x_h);    uint32_t* xl   = symaddr<uint32_t>(g_x_l);
    uint32_t* qh   = symaddr<uint32_t>(g_qkv_h);  uint32_t* ql   = symaddr<uint32_t>(g_qkv_l);
    uint32_t* sch  = symaddr<uint32_t>(g_sc_h);   uint32_t* scl  = symaddr<uint32_t>(g_sc_l);
    uint32_t* aoh  = symaddr<uint32_t>(g_ao_h);   uint32_t* aol  = symaddr<uint32_t>(g_ao_l);
    uint32_t* mih  = symaddr<uint32_t>(g_mid_h);  uint32_t* mil  = symaddr<uint32_t>(g_mid_l);
    uint32_t* wqh  = symaddr<uint32_t>(g_wqkv_h); uint32_t* wql  = symaddr<uint32_t>(g_wqkv_l);
    uint32_t* woh  = symaddr<uint32_t>(g_wo_h);   uint32_t* wol  = symaddr<uint32_t>(g_wo_l);
    uint32_t* w1h  = symaddr<uint32_t>(g_w1_h);   uint32_t* w1l  = symaddr<uint32_t>(g_w1_l);
    uint32_t* w2h  = symaddr<uint32_t>(g_w2_h);   uint32_t* w2l  = symaddr<uint32_t>(g_w2_l);

    cudaMemsetAsync(zp, 0, (size_t)ZSZ * sizeof(float), 0);

    // split weights once per launch
    conv_kernel<<<(C3 * CCP + 255) / 256, 256>>>(in_proj_w,  wqh, wql, C3 * CCP);
    conv_kernel<<<(CC * CCP + 255) / 256, 256>>>(out_proj_w, woh, wol, CC * CCP);
    conv_kernel<<<(C4 * CCP + 255) / 256, 256>>>(mlp_w1,     w1h, w1l, C4 * CCP);
    conv_kernel<<<(CC * C4P + 255) / 256, 256>>>(mlp_w2,     w2h, w2l, CC * C4P);

    for (int it = 0; it < NUM_ITERS; it++) {
        // x = LN1(z + 0.1*emb[it] + u) -> planes
        ln_kernel<<<BT, 256>>>(zp, u, iter_emb + it * CC, ln1_w, ln1_b, xh, xl);

        // qkv = x @ Wqkv^T + b  -> planes
        mma_gemm<0, false, true><<<dim3(C3 / 64, BT / 128, 1), 256>>>(
            xh, xl, wqh, wql, in_proj_b, nullptr, qh, ql,
            CC, CCP, CCP, C3P, 0, 0, 0, 0, 0, 0, nullptr, nullptr);

        // scores = Q K^T / 8  (fp32, batched over B*H)
        mma_gemm<4, false, false><<<dim3(TT / 64, TT / 128, BB * HH), 256>>>(
            qh, ql, qh + CCP, ql + CCP, nullptr, scp, nullptr, nullptr,
            DH, C3P, C3P, TT,
            (long)TT * C3P, DHP, (long)TT * C3P, DHP,
            (long)HH * TT * TT, (long)TT * TT, nullptr, nullptr);

        softmax_kernel<<<BB * HH * TT, 256>>>(scp, sch, scl);

        // attnout = att @ V  -> planes (V repacked from qkv planes)
        mma_gemm<5, true, true><<<dim3(1, TT / 128, BB * HH), 256>>>(
            sch, scl, qh + 2 * CCP, ql + 2 * CCP, nullptr, nullptr, aoh, aol,
            TT, TTP, C3P, CCP,
            (long)HH * TT * TTP, (long)TT * TTP, (long)TT * C3P, DHP,
            (long)TT * CCP, DHP, nullptr, nullptr);

        // z_attn = z + attnout @ Wo^T + bo  (fp32)
        mma_gemm<2, false, false><<<dim3(CC / 64, BT / 128, 1), 256>>>(
            aoh, aol, woh, wol, out_proj_b, zap, nullptr, nullptr,
            CC, CCP, CCP, CC, 0, 0, 0, 0, 0, 0, zp, nullptr);

        // h = LN2(z_attn) -> planes
        ln_kernel<<<BT, 256>>>(zap, nullptr, nullptr, ln2_w, ln2_b, xh, xl);

        // mid = gelu(h @ W1^T + b1) -> planes
        mma_gemm<1, false, true><<<dim3(C4 / 64, BT / 128, 1), 256>>>(
            xh, xl, w1h, w1l, mlp_b1, nullptr, mih, mil,
            CC, CCP, CCP, C4P, 0, 0, 0, 0, 0, 0, nullptr, nullptr);

        // res = (mid @ W2^T + b2) + z_attn - z  (fp32)
        mma_gemm<3, false, false><<<dim3(CC / 64, BT / 128, 1), 256>>>(
            mih, mil, w2h, w2l, mlp_b2, resp, nullptr, nullptr,
            C4, C4P, C4P, CC, 0, 0, 0, 0, 0, 0, zap, zp);

        // Anderson update of z, residual history push
        anderson_kernel<<<BT, 256>>>(zp, resp, fhp, it);
    }

    cudaMemcpyAsync(d_out, zp, (size_t)ZSZ * sizeof(float),
                    cudaMemcpyDeviceToDevice, 0);
}

// round 7
// speedup vs baseline: 2.3585x; 1.1573x over previous
#include <cuda_runtime.h>
#include <cuda_bf16.h>
#include <math.h>
#include <stdint.h>

// Problem constants (fixed by setup_inputs)
#define BB    4
#define TT    1024
#define CC    768
#define HH    12
#define DH    64
#define BT    4096            // B*T
#define C3    2304            // 3*C
#define C4    3072            // 4*C
#define ZSZ   3145728         // BT*C
#define NUM_ITERS 6
// pair (bf16x2) leading dims
#define CCP   384
#define C3P   1152
#define C4P   1536
#define TTP   512
#define DHP   32

// ---------------- scratch (device globals; no allocation allowed) -----------
__device__ float g_z[ZSZ];
__device__ float g_zattn[ZSZ];
__device__ float g_res[ZSZ];
__device__ float g_fhist[4 * ZSZ];
__device__ float g_scores[(size_t)BB * HH * TT * TT];      // fp32 logits (192MB)

// hi/lo bf16x2 planes (pairs packed along k)
__device__ uint32_t g_x_h[BT * CCP],    g_x_l[BT * CCP];
__device__ uint32_t g_qkv_h[BT * C3P],  g_qkv_l[BT * C3P];
__device__ uint32_t g_sc_h[(size_t)BB * HH * TT * TTP];
__device__ uint32_t g_sc_l[(size_t)BB * HH * TT * TTP];
__device__ uint32_t g_ao_h[BT * CCP],   g_ao_l[BT * CCP];
__device__ uint32_t g_mid_h[BT * C4P],  g_mid_l[BT * C4P];
// weight planes (split once per launch)
__device__ uint32_t g_wqkv_h[C3 * CCP], g_wqkv_l[C3 * CCP];
__device__ uint32_t g_wo_h[CC * CCP],   g_wo_l[CC * CCP];
__device__ uint32_t g_w1_h[C4 * CCP],   g_w1_l[C4 * CCP];
__device__ uint32_t g_w2_h[CC * C4P],   g_w2_l[CC * C4P];

// ---------------- helpers ------------------------------------------------------
__device__ __forceinline__ void split2(float x, float y, uint32_t& hi, uint32_t& lo) {
    __nv_bfloat162 h2 = __floats2bfloat162_rn(x, y);
    float lx = x - __low2float(h2);
    float ly = y - __high2float(h2);
    __nv_bfloat162 l2 = __floats2bfloat162_rn(lx, ly);
    hi = *reinterpret_cast<uint32_t*>(&h2);
    lo = *reinterpret_cast<uint32_t*>(&l2);
}

__device__ __forceinline__ void mma16(float c[4], const uint32_t a[4], const uint32_t b[2]) {
    asm volatile(
        "mma.sync.aligned.m16n8k16.row.col.f32.bf16.bf16.f32 "
        "{%0,%1,%2,%3}, {%4,%5,%6,%7}, {%8,%9}, {%0,%1,%2,%3};\n"
        : "+f"(c[0]), "+f"(c[1]), "+f"(c[2]), "+f"(c[3])
        : "r"(a[0]), "r"(a[1]), "r"(a[2]), "r"(a[3]), "r"(b[0]), "r"(b[1]));
}

__device__ __forceinline__ void ldm4(uint32_t r[4], uint32_t addr) {
    asm volatile("ldmatrix.sync.aligned.m8n8.x4.shared.b16 {%0,%1,%2,%3}, [%4];"
        : "=r"(r[0]), "=r"(r[1]), "=r"(r[2]), "=r"(r[3]) : "r"(addr));
}

__device__ __forceinline__ uint32_t smem_u32(const void* p) {
    return (uint32_t)__cvta_generic_to_shared(p);
}

// ---------------- weight/activation split kernel ------------------------------
__global__ void conv_kernel(const float* __restrict__ w,
                            uint32_t* __restrict__ h,
                            uint32_t* __restrict__ l, int npairs) {
    int i = blockIdx.x * 256 + threadIdx.x;
    if (i < npairs) {
        float2 x = ((const float2*)w)[i];
        uint32_t hv, lv;
        split2(x.x, x.y, hv, lv);
        h[i] = hv; l[i] = lv;
    }
}

// ---------------- unified tensor-core GEMM (bf16x3, pre-split planes) ---------
// out[m,n] = sum_k A[m,k] * B[n,k]   (planes pre-split, pairs packed along k).
// Tile: 128(M) x 64(N) x 16(K), 8 warps (4x2), warp tile 32x32.
// Fragment loads via ldmatrix.x4 (8 per warp per k-step).
// 3 MMA passes: hi*lo + lo*hi + hi*hi.
// MODE: 0 +bias | 1 gelu(+bias) | 2 +bias+add1 | 3 +bias+add1-add2 | 4 *0.125 | 5 none
template<int MODE, bool BTRANS, bool OUTP>
__global__ void __launch_bounds__(256) mma_gemm(
    const uint32_t* __restrict__ Agh, const uint32_t* __restrict__ Agl,
    const uint32_t* __restrict__ Bgh, const uint32_t* __restrict__ Bgl,
    const float* __restrict__ bias,
    float* __restrict__ outF, uint32_t* __restrict__ outH, uint32_t* __restrict__ outL,
    int K, int ldaP, int ldbP, int ldc,
    long aSB, long aSH, long bSB, long bSH, long oSB, long oSH,
    const float* __restrict__ add1, const float* __restrict__ add2)
{
    __shared__ __align__(16) uint32_t sAh[2][128][12], sAl[2][128][12];
    __shared__ __align__(16) uint32_t sBh[2][64][12],  sBl[2][64][12];

    {
        const int z = blockIdx.z;
        const int b = z / HH, h = z % HH;
        Agh += (size_t)b * aSB + (size_t)h * aSH;
        Agl += (size_t)b * aSB + (size_t)h * aSH;
        Bgh += (size_t)b * bSB + (size_t)h * bSH;
        Bgl += (size_t)b * bSB + (size_t)h * bSH;
        const size_t oo = (size_t)b * oSB + (size_t)h * oSH;
        if (OUTP) { outH += oo; outL += oo; }
        else      { outF += oo; }
        if (add1) add1 += oo;
        if (add2) add2 += oo;
    }
    const int tid  = threadIdx.x;
    const int lane = tid & 31;
    const int wid  = tid >> 5;
    const int wm   = wid >> 1;     // 0..3
    const int wn   = wid & 1;      // 0..1
    const int m0   = blockIdx.y * 128;
    const int n0   = blockIdx.x * 64;

    const int nsteps = K >> 4;     // k-steps of 16 elems = 8 pairs

    const int arow = tid >> 1;          // 0..127
    const int akq  = (tid & 1) << 2;    // 0 or 4 (pair units)

    // ldmatrix lane addresses (byte offsets within one plane buffer)
    // A: row = wm*32 + mt*16 + (lane&15), kbyte = (lane>>4)*16
    // B: row = wn*32 + ntp*16 + ((lane>>4)&1)*8 + (lane&7), kbyte = ((lane>>3)&1)*16
    const uint32_t sAh0 = smem_u32(&sAh[0][0][0]);
    const uint32_t sAl0 = smem_u32(&sAl[0][0][0]);
    const uint32_t sBh0 = smem_u32(&sBh[0][0][0]);
    const uint32_t sBl0 = smem_u32(&sBl[0][0][0]);
    const uint32_t aoff = (uint32_t)(wm * 32 + (lane & 15)) * 48 + (uint32_t)(lane >> 4) * 16;
    const uint32_t boff = (uint32_t)(wn * 32 + ((lane >> 4) & 1) * 8 + (lane & 7)) * 48 +
                          (uint32_t)((lane >> 3) & 1) * 16;

    // ---- loaders ---------------------------------------------------------------
    uint4 pah, pal, pbh, pbl;
    uint32_t vth[2], vtl[2];

    auto load_a = [&](int s) {
        const size_t off = (size_t)(m0 + arow) * ldaP + (s << 3) + akq;
        pah = *(const uint4*)(Agh + off);
        pal = *(const uint4*)(Agl + off);
    };
    auto store_a = [&](int buf) {
        *(uint4*)&sAh[buf][arow][akq] = pah;
        *(uint4*)&sAl[buf][arow][akq] = pal;
    };
    auto load_b = [&](int s) {
        if (!BTRANS) {
            if (tid < 128) {
                const int brow = tid >> 1;
                const size_t off = (size_t)(n0 + brow) * ldbP + (s << 3) + akq;
                pbh = *(const uint4*)(Bgh + off);
                pbl = *(const uint4*)(Bgl + off);
            }
        } else {
#pragma unroll
            for (int i = 0; i < 2; i++) {
                const int idx = tid + i * 256;
                const int n  = idx & 63;
                const int kp = idx >> 6;
                const size_t r0 = (size_t)((s << 4) + 2 * kp) * ldbP + ((n0 + n) >> 1);
                const uint32_t sel = (n & 1) ? 0x7632u : 0x5410u;
                uint32_t w0 = Bgh[r0],        w1 = Bgh[r0 + ldbP];
                vth[i] = __byte_perm(w0, w1, sel);
                w0 = Bgl[r0]; w1 = Bgl[r0 + ldbP];
                vtl[i] = __byte_perm(w0, w1, sel);
            }
        }
    };
    auto store_b = [&](int buf) {
        if (!BTRANS) {
            if (tid < 128) {
                const int brow = tid >> 1;
                *(uint4*)&sBh[buf][brow][akq] = pbh;
                *(uint4*)&sBl[buf][brow][akq] = pbl;
            }
        } else {
#pragma unroll
            for (int i = 0; i < 2; i++) {
                const int idx = tid + i * 256;
                const int n  = idx & 63;
                const int kp = idx >> 6;
                sBh[buf][n][kp] = vth[i];
                sBl[buf][n][kp] = vtl[i];
            }
        }
    };

    // ---- prologue ---------------------------------------------------------------
    load_a(0); load_b(0);
    store_a(0); store_b(0);
    __syncthreads();

    float acc[2][4][4];
#pragma unroll
    for (int i = 0; i < 2; i++)
#pragma unroll
        for (int j = 0; j < 4; j++)
#pragma unroll
            for (int e = 0; e < 4; e++) acc[i][j][e] = 0.0f;

    const int kp = lane & 3;
    const int qr = lane >> 2;

    for (int s = 0; s < nsteps; s++) {
        const int cur = s & 1;
        if (s + 1 < nsteps) { load_a(s + 1); load_b(s + 1); }

        const uint32_t bufA = (uint32_t)cur * (128 * 12 * 4);
        const uint32_t bufB = (uint32_t)cur * (64 * 12 * 4);

        uint32_t ah[2][4], al4[2][4];
#pragma unroll
        for (int mt = 0; mt < 2; mt++) {
            const uint32_t ao = aoff + (uint32_t)mt * (16 * 48);
            ldm4(ah[mt],  sAh0 + bufA + ao);
            ldm4(al4[mt], sAl0 + bufA + ao);
        }
        uint32_t bfh[2][4], bfl[2][4];
#pragma unroll
        for (int ntp = 0; ntp < 2; ntp++) {
            const uint32_t bo = boff + (uint32_t)ntp * (16 * 48);
            ldm4(bfh[ntp], sBh0 + bufB + bo);
            ldm4(bfl[ntp], sBl0 + bufB + bo);
        }
#pragma unroll
        for (int mt = 0; mt < 2; mt++)
#pragma unroll
            for (int ntp = 0; ntp < 2; ntp++)
#pragma unroll
                for (int j = 0; j < 2; j++) {
                    const int nt = 2 * ntp + j;
                    mma16(acc[mt][nt], ah[mt],  &bfl[ntp][2 * j]);
                    mma16(acc[mt][nt], al4[mt], &bfh[ntp][2 * j]);
                    mma16(acc[mt][nt], ah[mt],  &bfh[ntp][2 * j]);
                }

        if (s + 1 < nsteps) {
            const int nb = cur ^ 1;
            store_a(nb); store_b(nb);
            __syncthreads();
        }
    }

    // ---- epilogue -----------------------------------------------------------------
#pragma unroll
    for (int mt = 0; mt < 2; mt++) {
#pragma unroll
        for (int nt = 0; nt < 4; nt++) {
            const int r = m0 + wm * 32 + mt * 16 + qr;
            const int c = n0 + wn * 32 + nt * 8 + 2 * kp;
            float vv[4];
#pragma unroll
            for (int e = 0; e < 4; e++) {
                const int cc = c + (e & 1);
                float v = acc[mt][nt][e];
                if (MODE <= 3) v += bias[cc];
                if (MODE == 1) v = 0.5f * v * (1.0f + erff(v * 0.70710678118654752f));
                if (MODE == 4) v *= 0.125f;
                vv[e] = v;
            }
            if (OUTP) {
                const int cp = c >> 1;
                uint32_t h0, l0, h1, l1;
                split2(vv[0], vv[1], h0, l0);
                split2(vv[2], vv[3], h1, l1);
                outH[(size_t)r * ldc + cp] = h0;       // ldc in pairs here
                outL[(size_t)r * ldc + cp] = l0;
                outH[(size_t)(r + 8) * ldc + cp] = h1;
                outL[(size_t)(r + 8) * ldc + cp] = l1;
            } else {
#pragma unroll
                for (int e = 0; e < 4; e++) {
                    const int rr = r + (e >> 1) * 8;
                    const int cc = c + (e & 1);
                    const size_t oidx = (size_t)rr * ldc + cc;
                    float v = vv[e];
                    if (MODE == 2) v += add1[oidx];
                    if (MODE == 3) v += add1[oidx] - add2[oidx];
                    outF[oidx] = v;
                }
            }
        }
    }
}

// ---------------- fused add + LayerNorm -> hi/lo planes -----------------------
__global__ void ln_kernel(const float* __restrict__ zin,
                          const float* __restrict__ u,
                          const float* __restrict__ emb,
                          const float* __restrict__ w,
                          const float* __restrict__ b,
                          uint32_t* __restrict__ oh,
                          uint32_t* __restrict__ ol) {
    __shared__ float red[256];
    const int row = blockIdx.x;
    const int tid = threadIdx.x;
    const size_t base = (size_t)row * CC;
    const float2* z2 = (const float2*)(zin + base);
    const float2* u2 = u ? (const float2*)(u + base) : nullptr;
    const float2* e2 = emb ? (const float2*)emb : nullptr;

    float2 va = z2[tid];
    float2 vb = make_float2(0.f, 0.f);
    if (u2) { float2 t = u2[tid]; va.x += t.x; va.y += t.y; }
    if (e2) { float2 t = e2[tid]; va.x += 0.1f * t.x; va.y += 0.1f * t.y; }
    if (tid < 128) {
        vb = z2[256 + tid];
        if (u2) { float2 t = u2[256 + tid]; vb.x += t.x; vb.y += t.y; }
        if (e2) { float2 t = e2[256 + tid]; vb.x += 0.1f * t.x; vb.y += 0.1f * t.y; }
    }
    float s = va.x + va.y + vb.x + vb.y;
    red[tid] = s; __syncthreads();
    for (int st = 128; st > 0; st >>= 1) {
        if (tid < st) red[tid] += red[tid + st];
        __syncthreads();
    }
    const float mu = red[0] * (1.0f / CC);
    __syncthreads();
    va.x -= mu; va.y -= mu;
    float s2 = va.x * va.x + va.y * va.y;
    if (tid < 128) { vb.x -= mu; vb.y -= mu; s2 += vb.x * vb.x + vb.y * vb.y; }
    red[tid] = s2; __syncthreads();
    for (int st = 128; st > 0; st >>= 1) {
        if (tid < st) red[tid] += red[tid + st];
        __syncthreads();
    }
    const float rs = rsqrtf(red[0] * (1.0f / CC) + 1e-5f);

    const float2* w2 = (const float2*)w;
    const float2* b2 = (const float2*)b;
    {
        float2 wc = w2[tid], bc = b2[tid];
        float y0 = va.x * rs * wc.x + bc.x;
        float y1 = va.y * rs * wc.y + bc.y;
        uint32_t hv, lv;
        split2(y0, y1, hv, lv);
        oh[(size_t)row * CCP + tid] = hv;
        ol[(size_t)row * CCP + tid] = lv;
    }
    if (tid < 128) {
        float2 wc = w2[256 + tid], bc = b2[256 + tid];
        float y0 = vb.x * rs * wc.x + bc.x;
        float y1 = vb.y * rs * wc.y + bc.y;
        uint32_t hv, lv;
        split2(y0, y1, hv, lv);
        oh[(size_t)row * CCP + 256 + tid] = hv;
        ol[(size_t)row * CCP + 256 + tid] = lv;
    }
}

// ---------------- softmax (fp32 in) -> hi/lo planes ---------------------------
__global__ void softmax_kernel(const float* __restrict__ sc,
                               uint32_t* __restrict__ oh,
                               uint32_t* __restrict__ ol) {
    __shared__ float red[256];
    const int tid = threadIdx.x;
    const size_t base = (size_t)blockIdx.x * TT;
    float4 v = ((const float4*)(sc + base))[tid];      // cols 4t..4t+3
    float m = fmaxf(fmaxf(v.x, v.y), fmaxf(v.z, v.w));
    red[tid] = m; __syncthreads();
    for (int st = 128; st > 0; st >>= 1) {
        if (tid < st) red[tid] = fmaxf(red[tid], red[tid + st]);
        __syncthreads();
    }
    m = red[0]; __syncthreads();
    v.x = __expf(v.x - m); v.y = __expf(v.y - m);
    v.z = __expf(v.z - m); v.w = __expf(v.w - m);
    red[tid] = v.x + v.y + v.z + v.w; __syncthreads();
    for (int st = 128; st > 0; st >>= 1) {
        if (tid < st) red[tid] += red[tid + st];
        __syncthreads();
    }
    const float inv = 1.0f / red[0];
    v.x *= inv; v.y *= inv; v.z *= inv; v.w *= inv;
    uint32_t h0, l0, h1, l1;
    split2(v.x, v.y, h0, l0);
    split2(v.z, v.w, h1, l1);
    const size_t pbase = (size_t)blockIdx.x * TTP;
    ((uint2*)(oh + pbase))[tid] = make_uint2(h0, h1);
    ((uint2*)(ol + pbase))[tid] = make_uint2(l0, l1);
}

// ---------------- Anderson acceleration update (one block per token) ---------
__global__ void anderson_kernel(float* __restrict__ z,
                                const float* __restrict__ res,
                                float* __restrict__ fh, int it) {
    __shared__ float sh[14][256];
    __shared__ float alpha_sh[4];
    const int n = blockIdx.x, tid = threadIdx.x;
    const size_t base = (size_t)n * CC;
    const int K = it < 4 ? it : 4;
    const int c0 = tid, c1 = tid + 256, c2 = tid + 512;

    float r0 = res[base + c0], r1 = res[base + c1], r2 = res[base + c2];
    float dF[4][3];
    for (int j = 0; j < K; j++) {
        const int slot = (it - K + j) & 3;
        const float* f = fh + (size_t)slot * ZSZ + base;
        dF[j][0] = f[c0] - r0; dF[j][1] = f[c1] - r1; dF[j][2] = f[c2] - r2;
    }

    if (K > 0) {
        int idx = 0;
        for (int k = 0; k < K; k++)
            for (int l = k; l < K; l++) {
                sh[idx][tid] = dF[k][0] * dF[l][0] + dF[k][1] * dF[l][1] + dF[k][2] * dF[l][2];
                idx++;
            }
        for (int k = 0; k < K; k++) {
            sh[idx][tid] = dF[k][0] * r0 + dF[k][1] * r1 + dF[k][2] * r2;
            idx++;
        }
        const int np = idx;
        __syncthreads();
        for (int st = 128; st > 0; st >>= 1) {
            if (tid < st)
                for (int v = 0; v < np; v++) sh[v][tid] += sh[v][tid + st];
            __syncthreads();
        }
        if (tid == 0) {
            float G[4][4], bv[4], al[4];
            int id2 = 0;
            for (int k = 0; k < K; k++)
                for (int l = k; l < K; l++) { G[k][l] = G[l][k] = sh[id2][0]; id2++; }
            for (int k = 0; k < K; k++) { G[k][k] += 1e-6f; bv[k] = sh[id2][0]; id2++; }
            for (int p = 0; p < K; p++) {
                const float inv = 1.0f / G[p][p];
                for (int rr = p + 1; rr < K; rr++) {
                    const float f2 = G[rr][p] * inv;
                    for (int cc = p; cc < K; cc++) G[rr][cc] -= f2 * G[p][cc];
                    bv[rr] -= f2 * bv[p];
                }
            }
            for (int p = K - 1; p >= 0; p--) {
                float s = bv[p];
                for (int cc = p + 1; cc < K; cc++) s -= G[p][cc] * al[cc];
                al[p] = s / G[p][p];
            }
            for (int k = 0; k < K; k++) alpha_sh[k] = al[k];
        }
        __syncthreads();
        float d0 = r0, d1 = r1, d2 = r2;
        for (int j = 0; j < K; j++) {
            const float a = alpha_sh[j];
            d0 -= a * dF[j][0]; d1 -= a * dF[j][1]; d2 -= a * dF[j][2];
        }
        z[base + c0] += d0; z[base + c1] += d1; z[base + c2] += d2;
    } else {
        z[base + c0] += r0; z[base + c1] += r1; z[base + c2] += r2;
    }

    float* fs = fh + (size_t)(it & 3) * ZSZ + base;
    fs[c0] = r0; fs[c1] = r1; fs[c2] = r2;
}

// ---------------- host launcher ----------------------------------------------
template <typename T>
static T* symaddr(const void* s) {
    void* p = nullptr;
    cudaGetSymbolAddress(&p, s);
    return (T*)p;
}

extern "C" void kernel_launch(void* const* d_in, const int* in_sizes, int n_in,
                              void* d_out, int out_size) {
    const float* u          = (const float*)d_in[0];
    const float* iter_emb   = (const float*)d_in[1];
    const float* ln1_w      = (const float*)d_in[2];
    const float* ln1_b      = (const float*)d_in[3];
    const float* in_proj_w  = (const float*)d_in[4];
    const float* in_proj_b  = (const float*)d_in[5];
    const float* out_proj_w = (const float*)d_in[6];
    const float* out_proj_b = (const float*)d_in[7];
    const float* ln2_w      = (const float*)d_in[8];
    const float* ln2_b      = (const float*)d_in[9];
    const float* mlp_w1     = (const float*)d_in[10];
    const float* mlp_b1     = (const float*)d_in[11];
    const float* mlp_w2     = (const float*)d_in[12];
    const float* mlp_b2     = (const float*)d_in[13];
    // d_in[14] = num_iters (fixed to 6 by setup_inputs)

    float* zp   = symaddr<float>(g_z);
    float* zap  = symaddr<float>(g_zattn);
    float* resp = symaddr<float>(g_res);
    float* fhp  = symaddr<float>(g_fhist);
    float* scp  = symaddr<float>(g_scores);
    uint32_t* xh   = symaddr<uint32_t>(g_x_h);    uint32_t* xl   = symaddr<uint32_t>(g_x_l);
    uint32_t* qh   = symaddr<uint32_t>(g_qkv_h);  uint32_t* ql   = symaddr<uint32_t>(g_qkv_l);
    uint32_t* sch  = symaddr<uint32_t>(g_sc_h);   uint32_t* scl  = symaddr<uint32_t>(g_sc_l);
    uint32_t* aoh  = symaddr<uint32_t>(g_ao_h);   uint32_t* aol  = symaddr<uint32_t>(g_ao_l);
    uint32_t* mih  = symaddr<uint32_t>(g_mid_h);  uint32_t* mil  = symaddr<uint32_t>(g_mid_l);
    uint32_t* wqh  = symaddr<uint32_t>(g_wqkv_h); uint32_t* wql  = symaddr<uint32_t>(g_wqkv_l);
    uint32_t* woh  = symaddr<uint32_t>(g_wo_h);   uint32_t* wol  = symaddr<uint32_t>(g_wo_l);
    uint32_t* w1h  = symaddr<uint32_t>(g_w1_h);   uint32_t* w1l  = symaddr<uint32_t>(g_w1_l);
    uint32_t* w2h  = symaddr<uint32_t>(g_w2_h);   uint32_t* w2l  = symaddr<uint32_t>(g_w2_l);

    cudaMemsetAsync(zp, 0, (size_t)ZSZ * sizeof(float), 0);

    // split weights once per launch
    conv_kernel<<<(C3 * CCP + 255) / 256, 256>>>(in_proj_w,  wqh, wql, C3 * CCP);
    conv_kernel<<<(CC * CCP + 255) / 256, 256>>>(out_proj_w, woh, wol, CC * CCP);
    conv_kernel<<<(C4 * CCP + 255) / 256, 256>>>(mlp_w1,     w1h, w1l, C4 * CCP);
    conv_kernel<<<(CC * C4P + 255) / 256, 256>>>(mlp_w2,     w2h, w2l, CC * C4P);

    for (int it = 0; it < NUM_ITERS; it++) {
        // x = LN1(z + 0.1*emb[it] + u) -> planes
        ln_kernel<<<BT, 256>>>(zp, u, iter_emb + it * CC, ln1_w, ln1_b, xh, xl);

        // qkv = x @ Wqkv^T + b  -> planes
        mma_gemm<0, false, true><<<dim3(C3 / 64, BT / 128, 1), 256>>>(
            xh, xl, wqh, wql, in_proj_b, nullptr, qh, ql,
            CC, CCP, CCP, C3P, 0, 0, 0, 0, 0, 0, nullptr, nullptr);

        // scores = Q K^T / 8  (fp32, batched over B*H)
        mma_gemm<4, false, false><<<dim3(TT / 64, TT / 128, BB * HH), 256>>>(
            qh, ql, qh + CCP, ql + CCP, nullptr, scp, nullptr, nullptr,
            DH, C3P, C3P, TT,
            (long)TT * C3P, DHP, (long)TT * C3P, DHP,
            (long)HH * TT * TT, (long)TT * TT, nullptr, nullptr);

        softmax_kernel<<<BB * HH * TT, 256>>>(scp, sch, scl);

        // attnout = att @ V  -> planes (V repacked from qkv planes)
        mma_gemm<5, true, true><<<dim3(1, TT / 128, BB * HH), 256>>>(
            sch, scl, qh + 2 * CCP, ql + 2 * CCP, nullptr, nullptr, aoh, aol,
            TT, TTP, C3P, CCP,
            (long)HH * TT * TTP, (long)TT * TTP, (long)TT * C3P, DHP,
            (long)TT * CCP, DHP, nullptr, nullptr);

        // z_attn = z + attnout @ Wo^T + bo  (fp32)
        mma_gemm<2, false, false><<<dim3(CC / 64, BT / 128, 1), 256>>>(
            aoh, aol, woh, wol, out_proj_b, zap, nullptr, nullptr,
            CC, CCP, CCP, CC, 0, 0, 0, 0, 0, 0, zp, nullptr);

        // h = LN2(z_attn) -> planes
        ln_kernel<<<BT, 256>>>(zap, nullptr, nullptr, ln2_w, ln2_b, xh, xl);

        // mid = gelu(h @ W1^T + b1) -> planes
        mma_gemm<1, false, true><<<dim3(C4 / 64, BT / 128, 1), 256>>>(
            xh, xl, w1h, w1l, mlp_b1, nullptr, mih, mil,
            CC, CCP, CCP, C4P, 0, 0, 0, 0, 0, 0, nullptr, nullptr);

        // res = (mid @ W2^T + b2) + z_attn - z  (fp32)
        mma_gemm<3, false, false><<<dim3(CC / 64, BT / 128, 1), 256>>>(
            mih, mil, w2h, w2l, mlp_b2, resp, nullptr, nullptr,
            C4, C4P, C4P, CC, 0, 0, 0, 0, 0, 0, zap, zp);

        // Anderson update of z, residual history push
        anderson_kernel<<<BT, 256>>>(zp, resp, fhp, it);
    }

    cudaMemcpyAsync(d_out, zp, (size_t)ZSZ * sizeof(float),
                    cudaMemcpyDeviceToDevice, 0);
}

// round 8
// speedup vs baseline: 2.8737x; 1.2185x over previous
#include <cuda_runtime.h>
#include <cuda_bf16.h>
#include <math.h>
#include <stdint.h>

// Problem constants (fixed by setup_inputs)
#define BB    4
#define TT    1024
#define CC    768
#define HH    12
#define DH    64
#define BT    4096            // B*T
#define C3    2304            // 3*C
#define C4    3072            // 4*C
#define ZSZ   3145728         // BT*C
#define NUM_ITERS 6
// pair (bf16x2) leading dims
#define CCP   384
#define C3P   1152
#define C4P   1536
#define TTP   512
#define DHP   32

// ---------------- scratch (device globals; no allocation allowed) -----------
__device__ float g_z[ZSZ];
__device__ float g_zattn[ZSZ];
__device__ float g_res[ZSZ];
__device__ float g_fhist[4 * ZSZ];
__device__ float g_scores[(size_t)BB * HH * TT * TT];      // fp32 logits (192MB)

// hi/lo bf16x2 planes (pairs packed along k)
__device__ uint32_t g_x_h[BT * CCP],    g_x_l[BT * CCP];
__device__ uint32_t g_qkv_h[BT * C3P],  g_qkv_l[BT * C3P];
__device__ uint32_t g_sc_h[(size_t)BB * HH * TT * TTP];
__device__ uint32_t g_sc_l[(size_t)BB * HH * TT * TTP];
__device__ uint32_t g_ao_h[BT * CCP],   g_ao_l[BT * CCP];
__device__ uint32_t g_mid_h[BT * C4P],  g_mid_l[BT * C4P];
// weight planes (split once per launch)
__device__ uint32_t g_wqkv_h[C3 * CCP], g_wqkv_l[C3 * CCP];
__device__ uint32_t g_wo_h[CC * CCP],   g_wo_l[CC * CCP];
__device__ uint32_t g_w1_h[C4 * CCP],   g_w1_l[C4 * CCP];
__device__ uint32_t g_w2_h[CC * C4P],   g_w2_l[CC * C4P];

// ---------------- helpers ------------------------------------------------------
__device__ __forceinline__ void split2(float x, float y, uint32_t& hi, uint32_t& lo) {
    __nv_bfloat162 h2 = __floats2bfloat162_rn(x, y);
    float lx = x - __low2float(h2);
    float ly = y - __high2float(h2);
    __nv_bfloat162 l2 = __floats2bfloat162_rn(lx, ly);
    hi = *reinterpret_cast<uint32_t*>(&h2);
    lo = *reinterpret_cast<uint32_t*>(&l2);
}

__device__ __forceinline__ void mma16(float c[4], const uint32_t a[4], const uint32_t b[2]) {
    asm volatile(
        "mma.sync.aligned.m16n8k16.row.col.f32.bf16.bf16.f32 "
        "{%0,%1,%2,%3}, {%4,%5,%6,%7}, {%8,%9}, {%0,%1,%2,%3};\n"
        : "+f"(c[0]), "+f"(c[1]), "+f"(c[2]), "+f"(c[3])
        : "r"(a[0]), "r"(a[1]), "r"(a[2]), "r"(a[3]), "r"(b[0]), "r"(b[1]));
}

__device__ __forceinline__ void ldm4(uint32_t r[4], uint32_t addr) {
    asm volatile("ldmatrix.sync.aligned.m8n8.x4.shared.b16 {%0,%1,%2,%3}, [%4];"
        : "=r"(r[0]), "=r"(r[1]), "=r"(r[2]), "=r"(r[3]) : "r"(addr));
}

__device__ __forceinline__ uint32_t smem_u32(const void* p) {
    return (uint32_t)__cvta_generic_to_shared(p);
}

__device__ __forceinline__ void cp16(uint32_t dst, const uint32_t* src) {
    asm volatile("cp.async.cg.shared.global [%0], [%1], 16;" :: "r"(dst), "l"(src));
}
#define CP_COMMIT() asm volatile("cp.async.commit_group;" ::: "memory")
#define CP_WAIT2()  asm volatile("cp.async.wait_group 2;" ::: "memory")

// ---------------- weight/activation split kernel ------------------------------
__global__ void conv_kernel(const float* __restrict__ w,
                            uint32_t* __restrict__ h,
                            uint32_t* __restrict__ l, int npairs) {
    int i = blockIdx.x * 256 + threadIdx.x;
    if (i < npairs) {
        float2 x = ((const float2*)w)[i];
        uint32_t hv, lv;
        split2(x.x, x.y, hv, lv);
        h[i] = hv; l[i] = lv;
    }
}

// ---------------- unified tensor-core GEMM (bf16x3, cp.async 4-stage) ---------
// out[m,n] = sum_k A[m,k] * B[n,k]   (planes pre-split, pairs packed along k).
// Tile: 128(M) x 64(N) x 16(K), 8 warps (4x2), warp tile 32x32.
// 4-stage cp.async pipeline; ldmatrix.x4 fragment loads; bf16x3 MMA passes.
// MODE: 0 +bias | 1 gelu(+bias) | 2 +bias+add1 | 3 +bias+add1-add2 | 4 *0.125 | 5 none
template<int MODE, bool BTRANS, bool OUTP>
__global__ void __launch_bounds__(256) mma_gemm(
    const uint32_t* __restrict__ Agh, const uint32_t* __restrict__ Agl,
    const uint32_t* __restrict__ Bgh, const uint32_t* __restrict__ Bgl,
    const float* __restrict__ bias,
    float* __restrict__ outF, uint32_t* __restrict__ outH, uint32_t* __restrict__ outL,
    int K, int ldaP, int ldbP, int ldc,
    long aSB, long aSH, long bSB, long bSH, long oSB, long oSH,
    const float* __restrict__ add1, const float* __restrict__ add2)
{
    extern __shared__ __align__(16) uint32_t dsm[];
    // stage layout (words): Ah[128][12]=1536 | Al=1536 | Bh[64][12]=768 | Bl=768
    constexpr uint32_t STW     = 4608;       // words/stage
    constexpr uint32_t STB     = 18432;      // bytes/stage
    constexpr uint32_t OFF_AL  = 6144;       // bytes
    constexpr uint32_t OFF_BH  = 12288;
    constexpr uint32_t OFF_BL  = 15360;

    {
        const int z = blockIdx.z;
        const int b = z / HH, h = z % HH;
        Agh += (size_t)b * aSB + (size_t)h * aSH;
        Agl += (size_t)b * aSB + (size_t)h * aSH;
        Bgh += (size_t)b * bSB + (size_t)h * bSH;
        Bgl += (size_t)b * bSB + (size_t)h * bSH;
        const size_t oo = (size_t)b * oSB + (size_t)h * oSH;
        if (OUTP) { outH += oo; outL += oo; }
        else      { outF += oo; }
        if (add1) add1 += oo;
        if (add2) add2 += oo;
    }
    const int tid  = threadIdx.x;
    const int lane = tid & 31;
    const int wid  = tid >> 5;
    const int wm   = wid >> 1;     // 0..3
    const int wn   = wid & 1;      // 0..1
    const int m0   = blockIdx.y * 128;
    const int n0   = blockIdx.x * 64;

    const int nsteps = K >> 4;     // k-steps of 16 elems = 8 pairs

    const int arow = tid >> 1;          // 0..127
    const int akq  = (tid & 1) << 2;    // 0 or 4 (pair units)

    const uint32_t smb = smem_u32(dsm);
    const uint32_t aoff = (uint32_t)(wm * 32 + (lane & 15)) * 48 + (uint32_t)(lane >> 4) * 16;
    const uint32_t boff = (uint32_t)(wn * 32 + ((lane >> 4) & 1) * 8 + (lane & 7)) * 48 +
                          (uint32_t)((lane >> 3) & 1) * 16;

    // ---- async issue: A always, B when !BTRANS --------------------------------
    auto issue = [&](int s) {
        const uint32_t stb = smb + (uint32_t)(s & 3) * STB;
        const size_t aog = (size_t)(m0 + arow) * ldaP + (s << 3) + akq;
        const uint32_t adst = stb + (uint32_t)arow * 48 + (uint32_t)akq * 4;
        cp16(adst, Agh + aog);
        cp16(adst + OFF_AL, Agl + aog);
        if (!BTRANS) {
            if (tid < 128) {
                const int br = tid >> 1;
                const size_t bog = (size_t)(n0 + br) * ldbP + (s << 3) + akq;
                const uint32_t bdst = stb + OFF_BH + (uint32_t)br * 48 + (uint32_t)akq * 4;
                cp16(bdst, Bgh + bog);
                cp16(bdst + (OFF_BL - OFF_BH), Bgl + bog);
            }
        }
    };

    // ---- BTRANS B: register-pipelined gather + byte_perm repack ----------------
    uint32_t vth[2], vtl[2];
    auto loadBT = [&](int s) {
#pragma unroll
        for (int i = 0; i < 2; i++) {
            const int idx = tid + i * 256;
            const int n  = idx & 63;
            const int kpp = idx >> 6;
            const size_t r0 = (size_t)((s << 4) + 2 * kpp) * ldbP + ((n0 + n) >> 1);
            const uint32_t sel = (n & 1) ? 0x7632u : 0x5410u;
            vth[i] = __byte_perm(Bgh[r0], Bgh[r0 + ldbP], sel);
            vtl[i] = __byte_perm(Bgl[r0], Bgl[r0 + ldbP], sel);
        }
    };
    auto storeBT = [&](int s) {
        uint32_t* base = dsm + (size_t)(s & 3) * STW;
#pragma unroll
        for (int i = 0; i < 2; i++) {
            const int idx = tid + i * 256;
            const int n  = idx & 63;
            const int kpp = idx >> 6;
            base[3072 + n * 12 + kpp] = vth[i];
            base[3840 + n * 12 + kpp] = vtl[i];
        }
    };

    // ---- prologue: stages 0..2 ---------------------------------------------------
    if (BTRANS) {
        if (0 < nsteps) { loadBT(0); storeBT(0); }
        if (1 < nsteps) { loadBT(1); storeBT(1); }
    }
#pragma unroll
    for (int s = 0; s < 3; s++) {
        if (s < nsteps) issue(s);
        CP_COMMIT();
    }
    if (BTRANS && 2 < nsteps) loadBT(2);

    float acc[2][4][4];
#pragma unroll
    for (int i = 0; i < 2; i++)
#pragma unroll
        for (int j = 0; j < 4; j++)
#pragma unroll
            for (int e = 0; e < 4; e++) acc[i][j][e] = 0.0f;

    const int kp = lane & 3;
    const int qr = lane >> 2;

    for (int s = 0; s < nsteps; s++) {
        CP_WAIT2();
        __syncthreads();
        if (BTRANS) {
            if (s + 2 < nsteps) storeBT(s + 2);   // regs from prev iteration
            if (s + 3 < nsteps) loadBT(s + 3);
        }
        if (s + 3 < nsteps) issue(s + 3);
        CP_COMMIT();                               // always commit (uniform groups)

        const uint32_t stb = smb + (uint32_t)(s & 3) * STB;
        uint32_t ah[2][4], al4[2][4];
#pragma unroll
        for (int mt = 0; mt < 2; mt++) {
            const uint32_t ao = aoff + (uint32_t)mt * 768;
            ldm4(ah[mt],  stb + ao);
            ldm4(al4[mt], stb + OFF_AL + ao);
        }
        uint32_t bfh[2][4], bfl[2][4];
#pragma unroll
        for (int ntp = 0; ntp < 2; ntp++) {
            const uint32_t bo = boff + (uint32_t)ntp * 768;
            ldm4(bfh[ntp], stb + OFF_BH + bo);
            ldm4(bfl[ntp], stb + OFF_BL + bo);
        }
#pragma unroll
        for (int mt = 0; mt < 2; mt++)
#pragma unroll
            for (int ntp = 0; ntp < 2; ntp++)
#pragma unroll
                for (int j = 0; j < 2; j++) {
                    const int nt = 2 * ntp + j;
                    mma16(acc[mt][nt], ah[mt],  &bfl[ntp][2 * j]);
                    mma16(acc[mt][nt], al4[mt], &bfh[ntp][2 * j]);
                    mma16(acc[mt][nt], ah[mt],  &bfh[ntp][2 * j]);
                }
    }

    // ---- epilogue -----------------------------------------------------------------
#pragma unroll
    for (int mt = 0; mt < 2; mt++) {
#pragma unroll
        for (int nt = 0; nt < 4; nt++) {
            const int r = m0 + wm * 32 + mt * 16 + qr;
            const int c = n0 + wn * 32 + nt * 8 + 2 * kp;
            float vv[4];
#pragma unroll
            for (int e = 0; e < 4; e++) {
                const int cc = c + (e & 1);
                float v = acc[mt][nt][e];
                if (MODE <= 3) v += bias[cc];
                if (MODE == 1) v = 0.5f * v * (1.0f + erff(v * 0.70710678118654752f));
                if (MODE == 4) v *= 0.125f;
                vv[e] = v;
            }
            if (OUTP) {
                const int cp = c >> 1;
                uint32_t h0, l0, h1, l1;
                split2(vv[0], vv[1], h0, l0);
                split2(vv[2], vv[3], h1, l1);
                outH[(size_t)r * ldc + cp] = h0;       // ldc in pairs here
                outL[(size_t)r * ldc + cp] = l0;
                outH[(size_t)(r + 8) * ldc + cp] = h1;
                outL[(size_t)(r + 8) * ldc + cp] = l1;
            } else {
#pragma unroll
                for (int e = 0; e < 4; e++) {
                    const int rr = r + (e >> 1) * 8;
                    const int cc = c + (e & 1);
                    const size_t oidx = (size_t)rr * ldc + cc;
                    float v = vv[e];
                    if (MODE == 2) v += add1[oidx];
                    if (MODE == 3) v += add1[oidx] - add2[oidx];
                    outF[oidx] = v;
                }
            }
        }
    }
}

// ---------------- fused add + LayerNorm -> hi/lo planes -----------------------
__global__ void ln_kernel(const float* __restrict__ zin,
                          const float* __restrict__ u,
                          const float* __restrict__ emb,
                          const float* __restrict__ w,
                          const float* __restrict__ b,
                          uint32_t* __restrict__ oh,
                          uint32_t* __restrict__ ol) {
    __shared__ float red[256];
    const int row = blockIdx.x;
    const int tid = threadIdx.x;
    const size_t base = (size_t)row * CC;
    const float2* z2 = (const float2*)(zin + base);
    const float2* u2 = u ? (const float2*)(u + base) : nullptr;
    const float2* e2 = emb ? (const float2*)emb : nullptr;

    float2 va = z2[tid];
    float2 vb = make_float2(0.f, 0.f);
    if (u2) { float2 t = u2[tid]; va.x += t.x; va.y += t.y; }
    if (e2) { float2 t = e2[tid]; va.x += 0.1f * t.x; va.y += 0.1f * t.y; }
    if (tid < 128) {
        vb = z2[256 + tid];
        if (u2) { float2 t = u2[256 + tid]; vb.x += t.x; vb.y += t.y; }
        if (e2) { float2 t = e2[256 + tid]; vb.x += 0.1f * t.x; vb.y += 0.1f * t.y; }
    }
    float s = va.x + va.y + vb.x + vb.y;
    red[tid] = s; __syncthreads();
    for (int st = 128; st > 0; st >>= 1) {
        if (tid < st) red[tid] += red[tid + st];
        __syncthreads();
    }
    const float mu = red[0] * (1.0f / CC);
    __syncthreads();
    va.x -= mu; va.y -= mu;
    float s2 = va.x * va.x + va.y * va.y;
    if (tid < 128) { vb.x -= mu; vb.y -= mu; s2 += vb.x * vb.x + vb.y * vb.y; }
    red[tid] = s2; __syncthreads();
    for (int st = 128; st > 0; st >>= 1) {
        if (tid < st) red[tid] += red[tid + st];
        __syncthreads();
    }
    const float rs = rsqrtf(red[0] * (1.0f / CC) + 1e-5f);

    const float2* w2 = (const float2*)w;
    const float2* b2 = (const float2*)b;
    {
        float2 wc = w2[tid], bc = b2[tid];
        float y0 = va.x * rs * wc.x + bc.x;
        float y1 = va.y * rs * wc.y + bc.y;
        uint32_t hv, lv;
        split2(y0, y1, hv, lv);
        oh[(size_t)row * CCP + tid] = hv;
        ol[(size_t)row * CCP + tid] = lv;
    }
    if (tid < 128) {
        float2 wc = w2[256 + tid], bc = b2[256 + tid];
        float y0 = vb.x * rs * wc.x + bc.x;
        float y1 = vb.y * rs * wc.y + bc.y;
        uint32_t hv, lv;
        split2(y0, y1, hv, lv);
        oh[(size_t)row * CCP + 256 + tid] = hv;
        ol[(size_t)row * CCP + 256 + tid] = lv;
    }
}

// ---------------- softmax (fp32 in) -> hi/lo planes ---------------------------
__global__ void softmax_kernel(const float* __restrict__ sc,
                               uint32_t* __restrict__ oh,
                               uint32_t* __restrict__ ol) {
    __shared__ float red[256];
    const int tid = threadIdx.x;
    const size_t base = (size_t)blockIdx.x * TT;
    float4 v = ((const float4*)(sc + base))[tid];      // cols 4t..4t+3
    float m = fmaxf(fmaxf(v.x, v.y), fmaxf(v.z, v.w));
    red[tid] = m; __syncthreads();
    for (int st = 128; st > 0; st >>= 1) {
        if (tid < st) red[tid] = fmaxf(red[tid], red[tid + st]);
        __syncthreads();
    }
    m = red[0]; __syncthreads();
    v.x = __expf(v.x - m); v.y = __expf(v.y - m);
    v.z = __expf(v.z - m); v.w = __expf(v.w - m);
    red[tid] = v.x + v.y + v.z + v.w; __syncthreads();
    for (int st = 128; st > 0; st >>= 1) {
        if (tid < st) red[tid] += red[tid + st];
        __syncthreads();
    }
    const float inv = 1.0f / red[0];
    v.x *= inv; v.y *= inv; v.z *= inv; v.w *= inv;
    uint32_t h0, l0, h1, l1;
    split2(v.x, v.y, h0, l0);
    split2(v.z, v.w, h1, l1);
    const size_t pbase = (size_t)blockIdx.x * TTP;
    ((uint2*)(oh + pbase))[tid] = make_uint2(h0, h1);
    ((uint2*)(ol + pbase))[tid] = make_uint2(l0, l1);
}

// ---------------- Anderson acceleration update (one block per token) ---------
__global__ void anderson_kernel(float* __restrict__ z,
                                const float* __restrict__ res,
                                float* __restrict__ fh, int it) {
    __shared__ float sh[14][256];
    __shared__ float alpha_sh[4];
    const int n = blockIdx.x, tid = threadIdx.x;
    const size_t base = (size_t)n * CC;
    const int K = it < 4 ? it : 4;
    const int c0 = tid, c1 = tid + 256, c2 = tid + 512;

    float r0 = res[base + c0], r1 = res[base + c1], r2 = res[base + c2];
    float dF[4][3];
    for (int j = 0; j < K; j++) {
        const int slot = (it - K + j) & 3;
        const float* f = fh + (size_t)slot * ZSZ + base;
        dF[j][0] = f[c0] - r0; dF[j][1] = f[c1] - r1; dF[j][2] = f[c2] - r2;
    }

    if (K > 0) {
        int idx = 0;
        for (int k = 0; k < K; k++)
            for (int l = k; l < K; l++) {
                sh[idx][tid] = dF[k][0] * dF[l][0] + dF[k][1] * dF[l][1] + dF[k][2] * dF[l][2];
                idx++;
            }
        for (int k = 0; k < K; k++) {
            sh[idx][tid] = dF[k][0] * r0 + dF[k][1] * r1 + dF[k][2] * r2;
            idx++;
        }
        const int np = idx;
        __syncthreads();
        for (int st = 128; st > 0; st >>= 1) {
            if (tid < st)
                for (int v = 0; v < np; v++) sh[v][tid] += sh[v][tid + st];
            __syncthreads();
        }
        if (tid == 0) {
            float G[4][4], bv[4], al[4];
            int id2 = 0;
            for (int k = 0; k < K; k++)
                for (int l = k; l < K; l++) { G[k][l] = G[l][k] = sh[id2][0]; id2++; }
            for (int k = 0; k < K; k++) { G[k][k] += 1e-6f; bv[k] = sh[id2][0]; id2++; }
            for (int p = 0; p < K; p++) {
                const float inv = 1.0f / G[p][p];
                for (int rr = p + 1; rr < K; rr++) {
                    const float f2 = G[rr][p] * inv;
                    for (int cc = p; cc < K; cc++) G[rr][cc] -= f2 * G[p][cc];
                    bv[rr] -= f2 * bv[p];
                }
            }
            for (int p = K - 1; p >= 0; p--) {
                float s = bv[p];
                for (int cc = p + 1; cc < K; cc++) s -= G[p][cc] * al[cc];
                al[p] = s / G[p][p];
            }
            for (int k = 0; k < K; k++) alpha_sh[k] = al[k];
        }
        __syncthreads();
        float d0 = r0, d1 = r1, d2 = r2;
        for (int j = 0; j < K; j++) {
            const float a = alpha_sh[j];
            d0 -= a * dF[j][0]; d1 -= a * dF[j][1]; d2 -= a * dF[j][2];
        }
        z[base + c0] += d0; z[base + c1] += d1; z[base + c2] += d2;
    } else {
        z[base + c0] += r0; z[base + c1] += r1; z[base + c2] += r2;
    }

    float* fs = fh + (size_t)(it & 3) * ZSZ + base;
    fs[c0] = r0; fs[c1] = r1; fs[c2] = r2;
}

// ---------------- host launcher ----------------------------------------------
template <typename T>
static T* symaddr(const void* s) {
    void* p = nullptr;
    cudaGetSymbolAddress(&p, s);
    return (T*)p;
}

#define GEMM_SMEM 73728

extern "C" void kernel_launch(void* const* d_in, const int* in_sizes, int n_in,
                              void* d_out, int out_size) {
    const float* u          = (const float*)d_in[0];
    const float* iter_emb   = (const float*)d_in[1];
    const float* ln1_w      = (const float*)d_in[2];
    const float* ln1_b      = (const float*)d_in[3];
    const float* in_proj_w  = (const float*)d_in[4];
    const float* in_proj_b  = (const float*)d_in[5];
    const float* out_proj_w = (const float*)d_in[6];
    const float* out_proj_b = (const float*)d_in[7];
    const float* ln2_w      = (const float*)d_in[8];
    const float* ln2_b      = (const float*)d_in[9];
    const float* mlp_w1     = (const float*)d_in[10];
    const float* mlp_b1     = (const float*)d_in[11];
    const float* mlp_w2     = (const float*)d_in[12];
    const float* mlp_b2     = (const float*)d_in[13];
    // d_in[14] = num_iters (fixed to 6 by setup_inputs)

    float* zp   = symaddr<float>(g_z);
    float* zap  = symaddr<float>(g_zattn);
    float* resp = symaddr<float>(g_res);
    float* fhp  = symaddr<float>(g_fhist);
    float* scp  = symaddr<float>(g_scores);
    uint32_t* xh   = symaddr<uint32_t>(g_x_h);    uint32_t* xl   = symaddr<uint32_t>(g_x_l);
    uint32_t* qh   = symaddr<uint32_t>(g_qkv_h);  uint32_t* ql   = symaddr<uint32_t>(g_qkv_l);
    uint32_t* sch  = symaddr<uint32_t>(g_sc_h);   uint32_t* scl  = symaddr<uint32_t>(g_sc_l);
    uint32_t* aoh  = symaddr<uint32_t>(g_ao_h);   uint32_t* aol  = symaddr<uint32_t>(g_ao_l);
    uint32_t* mih  = symaddr<uint32_t>(g_mid_h);  uint32_t* mil  = symaddr<uint32_t>(g_mid_l);
    uint32_t* wqh  = symaddr<uint32_t>(g_wqkv_h); uint32_t* wql  = symaddr<uint32_t>(g_wqkv_l);
    uint32_t* woh  = symaddr<uint32_t>(g_wo_h);   uint32_t* wol  = symaddr<uint32_t>(g_wo_l);
    uint32_t* w1h  = symaddr<uint32_t>(g_w1_h);   uint32_t* w1l  = symaddr<uint32_t>(g_w1_l);
    uint32_t* w2h  = symaddr<uint32_t>(g_w2_h);   uint32_t* w2l  = symaddr<uint32_t>(g_w2_l);

    cudaFuncSetAttribute((const void*)mma_gemm<0, false, true>,  cudaFuncAttributeMaxDynamicSharedMemorySize, GEMM_SMEM);
    cudaFuncSetAttribute((const void*)mma_gemm<4, false, false>, cudaFuncAttributeMaxDynamicSharedMemorySize, GEMM_SMEM);
    cudaFuncSetAttribute((const void*)mma_gemm<5, true,  true>,  cudaFuncAttributeMaxDynamicSharedMemorySize, GEMM_SMEM);
    cudaFuncSetAttribute((const void*)mma_gemm<2, false, false>, cudaFuncAttributeMaxDynamicSharedMemorySize, GEMM_SMEM);
    cudaFuncSetAttribute((const void*)mma_gemm<1, false, true>,  cudaFuncAttributeMaxDynamicSharedMemorySize, GEMM_SMEM);
    cudaFuncSetAttribute((const void*)mma_gemm<3, false, false>, cudaFuncAttributeMaxDynamicSharedMemorySize, GEMM_SMEM);

    cudaMemsetAsync(zp, 0, (size_t)ZSZ * sizeof(float), 0);

    // split weights once per launch
    conv_kernel<<<(C3 * CCP + 255) / 256, 256>>>(in_proj_w,  wqh, wql, C3 * CCP);
    conv_kernel<<<(CC * CCP + 255) / 256, 256>>>(out_proj_w, woh, wol, CC * CCP);
    conv_kernel<<<(C4 * CCP + 255) / 256, 256>>>(mlp_w1,     w1h, w1l, C4 * CCP);
    conv_kernel<<<(CC * C4P + 255) / 256, 256>>>(mlp_w2,     w2h, w2l, CC * C4P);

    for (int it = 0; it < NUM_ITERS; it++) {
        // x = LN1(z + 0.1*emb[it] + u) -> planes
        ln_kernel<<<BT, 256>>>(zp, u, iter_emb + it * CC, ln1_w, ln1_b, xh, xl);

        // qkv = x @ Wqkv^T + b  -> planes
        mma_gemm<0, false, true><<<dim3(C3 / 64, BT / 128, 1), 256, GEMM_SMEM>>>(
            xh, xl, wqh, wql, in_proj_b, nullptr, qh, ql,
            CC, CCP, CCP, C3P, 0, 0, 0, 0, 0, 0, nullptr, nullptr);

        // scores = Q K^T / 8  (fp32, batched over B*H)
        mma_gemm<4, false, false><<<dim3(TT / 64, TT / 128, BB * HH), 256, GEMM_SMEM>>>(
            qh, ql, qh + CCP, ql + CCP, nullptr, scp, nullptr, nullptr,
            DH, C3P, C3P, TT,
            (long)TT * C3P, DHP, (long)TT * C3P, DHP,
            (long)HH * TT * TT, (long)TT * TT, nullptr, nullptr);

        softmax_kernel<<<BB * HH * TT, 256>>>(scp, sch, scl);

        // attnout = att @ V  -> planes (V repacked from qkv planes)
        mma_gemm<5, true, true><<<dim3(1, TT / 128, BB * HH), 256, GEMM_SMEM>>>(
            sch, scl, qh + 2 * CCP, ql + 2 * CCP, nullptr, nullptr, aoh, aol,
            TT, TTP, C3P, CCP,
            (long)HH * TT * TTP, (long)TT * TTP, (long)TT * C3P, DHP,
            (long)TT * CCP, DHP, nullptr, nullptr);

        // z_attn = z + attnout @ Wo^T + bo  (fp32)
        mma_gemm<2, false, false><<<dim3(CC / 64, BT / 128, 1), 256, GEMM_SMEM>>>(
            aoh, aol, woh, wol, out_proj_b, zap, nullptr, nullptr,
            CC, CCP, CCP, CC, 0, 0, 0, 0, 0, 0, zp, nullptr);

        // h = LN2(z_attn) -> planes
        ln_kernel<<<BT, 256>>>(zap, nullptr, nullptr, ln2_w, ln2_b, xh, xl);

        // mid = gelu(h @ W1^T + b1) -> planes
        mma_gemm<1, false, true><<<dim3(C4 / 64, BT / 128, 1), 256, GEMM_SMEM>>>(
            xh, xl, w1h, w1l, mlp_b1, nullptr, mih, mil,
            CC, CCP, CCP, C4P, 0, 0, 0, 0, 0, 0, nullptr, nullptr);

        // res = (mid @ W2^T + b2) + z_attn - z  (fp32)
        mma_gemm<3, false, false><<<dim3(CC / 64, BT / 128, 1), 256, GEMM_SMEM>>>(
            mih, mil, w2h, w2l, mlp_b2, resp, nullptr, nullptr,
            C4, C4P, C4P, CC, 0, 0, 0, 0, 0, 0, zap, zp);

        // Anderson update of z, residual history push
        anderson_kernel<<<BT, 256>>>(zp, resp, fhp, it);
    }

    cudaMemcpyAsync(d_out, zp, (size_t)ZSZ * sizeof(float),
                    cudaMemcpyDeviceToDevice, 0);
}

// round 9
// speedup vs baseline: 3.3916x; 1.1802x over previous
#include <cuda_runtime.h>
#include <cuda_bf16.h>
#include <math.h>
#include <stdint.h>

// Problem constants (fixed by setup_inputs)
#define BB    4
#define TT    1024
#define CC    768
#define HH    12
#define DH    64
#define BT    4096            // B*T
#define C3    2304            // 3*C
#define C4    3072            // 4*C
#define ZSZ   3145728         // BT*C
#define NUM_ITERS 6
// pair (bf16x2) leading dims
#define CCP   384
#define C3P   1152
#define C4P   1536
#define DHP   32

#define LOG2E 1.4426950408889634f
#define SEXP  0.18033688011112042f    // 0.125 * log2(e)

// ---------------- scratch (device globals; no allocation allowed) -----------
__device__ float g_z[ZSZ];
__device__ float g_zattn[ZSZ];
__device__ float g_res[ZSZ];
__device__ float g_fhist[4 * ZSZ];

// hi/lo bf16x2 planes (pairs packed along k)
__device__ uint32_t g_x_h[BT * CCP],    g_x_l[BT * CCP];
__device__ uint32_t g_qkv_h[BT * C3P],  g_qkv_l[BT * C3P];
__device__ uint32_t g_ao_h[BT * CCP],   g_ao_l[BT * CCP];
__device__ uint32_t g_mid_h[BT * C4P],  g_mid_l[BT * C4P];
// weight planes (split once per launch)
__device__ uint32_t g_wqkv_h[C3 * CCP], g_wqkv_l[C3 * CCP];
__device__ uint32_t g_wo_h[CC * CCP],   g_wo_l[CC * CCP];
__device__ uint32_t g_w1_h[C4 * CCP],   g_w1_l[C4 * CCP];
__device__ uint32_t g_w2_h[CC * C4P],   g_w2_l[CC * C4P];

// ---------------- helpers ------------------------------------------------------
__device__ __forceinline__ void split2(float x, float y, uint32_t& hi, uint32_t& lo) {
    __nv_bfloat162 h2 = __floats2bfloat162_rn(x, y);
    float lx = x - __low2float(h2);
    float ly = y - __high2float(h2);
    __nv_bfloat162 l2 = __floats2bfloat162_rn(lx, ly);
    hi = *reinterpret_cast<uint32_t*>(&h2);
    lo = *reinterpret_cast<uint32_t*>(&l2);
}

__device__ __forceinline__ void mma16(float c[4], const uint32_t a[4], const uint32_t b[2]) {
    asm volatile(
        "mma.sync.aligned.m16n8k16.row.col.f32.bf16.bf16.f32 "
        "{%0,%1,%2,%3}, {%4,%5,%6,%7}, {%8,%9}, {%0,%1,%2,%3};\n"
        : "+f"(c[0]), "+f"(c[1]), "+f"(c[2]), "+f"(c[3])
        : "r"(a[0]), "r"(a[1]), "r"(a[2]), "r"(a[3]), "r"(b[0]), "r"(b[1]));
}

__device__ __forceinline__ void ldm4(uint32_t r[4], uint32_t addr) {
    asm volatile("ldmatrix.sync.aligned.m8n8.x4.shared.b16 {%0,%1,%2,%3}, [%4];"
        : "=r"(r[0]), "=r"(r[1]), "=r"(r[2]), "=r"(r[3]) : "r"(addr));
}

__device__ __forceinline__ uint32_t smem_u32(const void* p) {
    return (uint32_t)__cvta_generic_to_shared(p);
}

__device__ __forceinline__ void cp16(uint32_t dst, const uint32_t* src) {
    asm volatile("cp.async.cg.shared.global [%0], [%1], 16;" :: "r"(dst), "l"(src));
}
#define CP_COMMIT() asm volatile("cp.async.commit_group;" ::: "memory")
#define CP_WAIT0()  asm volatile("cp.async.wait_group 0;" ::: "memory")
#define CP_WAIT2()  asm volatile("cp.async.wait_group 2;" ::: "memory")

// ---------------- weight/activation split kernel ------------------------------
__global__ void conv_kernel(const float* __restrict__ w,
                            uint32_t* __restrict__ h,
                            uint32_t* __restrict__ l, int npairs) {
    int i = blockIdx.x * 256 + threadIdx.x;
    if (i < npairs) {
        float2 x = ((const float2*)w)[i];
        uint32_t hv, lv;
        split2(x.x, x.y, hv, lv);
        h[i] = hv; l[i] = lv;
    }
}

// ---------------- flash attention (fused QK^T + softmax + AV) ------------------
// grid (TT/128, BB*HH), block 256 = 8 warps; warp w owns q-rows [w*16, w*16+16).
// K-loop: 16 tiles of 64 tokens. bf16x3 everywhere; O accum fp32 in registers.
// SMEM (words): K 2 stages @0 (Kh st*4608, Kl +2304) | Vh @9216 Vl @11520 |
//               P/Q: Ph @13824, Pl @18432.  Total 23040 words = 92160 B.
__global__ void __launch_bounds__(256) flash_attn(
    const uint32_t* __restrict__ qh_g, const uint32_t* __restrict__ ql_g,
    uint32_t* __restrict__ aoh, uint32_t* __restrict__ aol)
{
    extern __shared__ __align__(16) uint32_t dsm[];
    const int tid = threadIdx.x, lane = tid & 31, w = tid >> 5;
    const int bh = blockIdx.y, b = bh / HH, h = bh % HH;
    const int m0 = blockIdx.x * 128;
    const long tokb = (long)b * TT;
    const int hq = h * DHP;
    const int hk = CCP + h * DHP;
    const int hv = 2 * CCP + h * DHP;
    const uint32_t smb = smem_u32(dsm);
    const int qr = lane >> 2, kp = lane & 3;

    // ---- stage Q into P region and load register fragments ----
    for (int i = 0; i < 4; i++) {
        const int idx = tid + i * 256;            // 0..1023
        const int row = idx >> 3, ch = idx & 7;
        const size_t src = (size_t)(tokb + m0 + row) * C3P + hq + ch * 4;
        *(uint4*)&dsm[13824 + row * 36 + ch * 4] = *(const uint4*)(qh_g + src);
        *(uint4*)&dsm[18432 + row * 36 + ch * 4] = *(const uint4*)(ql_g + src);
    }
    __syncthreads();
    uint32_t qfh[4][4], qfl[4][4];
    {
        const uint32_t ao = smb + (uint32_t)(w * 16 + (lane & 15)) * 144 +
                            (uint32_t)(lane >> 4) * 16;
        for (int j = 0; j < 4; j++) {
            ldm4(qfh[j], ao + 13824 * 4 + j * 32);
            ldm4(qfl[j], ao + 18432 * 4 + j * 32);
        }
    }
    __syncthreads();                               // P region now reusable

    // ---- K prefetch via cp.async ----
    auto issueK = [&](int kt) {
        const uint32_t stb = smb + (uint32_t)(kt & 1) * (4608 * 4);
        for (int i = 0; i < 2; i++) {
            const int idx = tid + i * 256;         // 0..511
            const int row = idx >> 3, ch = idx & 7;
            const size_t src = (size_t)(tokb + kt * 64 + row) * C3P + hk + ch * 4;
            const uint32_t dst = stb + (uint32_t)row * 144 + (uint32_t)ch * 16;
            cp16(dst, qh_g + src);
            cp16(dst + 2304 * 4, ql_g + src);
        }
        CP_COMMIT();
    };
    issueK(0);

    float O[8][4];
#pragma unroll
    for (int nt = 0; nt < 8; nt++)
#pragma unroll
        for (int e = 0; e < 4; e++) O[nt][e] = 0.0f;
    float m0r = -1e30f, m1r = -1e30f, l0 = 0.0f, l1 = 0.0f;

    const uint32_t bof = (uint32_t)(((lane >> 4) & 1) * 8 + (lane & 7)) * 144 +
                         (uint32_t)((lane >> 3) & 1) * 16;
    const uint32_t aof = smb + (uint32_t)(w * 16 + (lane & 15)) * 144 +
                         (uint32_t)(lane >> 4) * 16;

    for (int kt = 0; kt < 16; kt++) {
        CP_WAIT0();
        __syncthreads();                           // sync A: K[kt] ready, prev AV done
        if (kt + 1 < 16) issueK(kt + 1);

        // ---- V transpose-repack for this tile (writes single V buffer) ----
#pragma unroll
        for (int i = 0; i < 8; i++) {
            const int gi = tid + i * 256;          // 0..2047
            const int d = gi & 63, tp = gi >> 6;
            const size_t r0 = (size_t)(tokb + kt * 64 + 2 * tp) * C3P + hv + (d >> 1);
            const uint32_t sel = (d & 1) ? 0x7632u : 0x5410u;
            dsm[9216 + d * 36 + tp]  = __byte_perm(qh_g[r0], qh_g[r0 + C3P], sel);
            dsm[11520 + d * 36 + tp] = __byte_perm(ql_g[r0], ql_g[r0 + C3P], sel);
        }

        // ---- S = Q K^T (raw, scale folded into exp) ----
        float sacc[8][4];
#pragma unroll
        for (int nt = 0; nt < 8; nt++)
#pragma unroll
            for (int e = 0; e < 4; e++) sacc[nt][e] = 0.0f;
        const uint32_t stb = smb + (uint32_t)(kt & 1) * (4608 * 4);
#pragma unroll
        for (int g = 0; g < 4; g++)
#pragma unroll
            for (int j = 0; j < 4; j++) {
                uint32_t kb[4], kl[4];
                ldm4(kb, stb + bof + g * (16 * 144) + j * 32);
                ldm4(kl, stb + 2304 * 4 + bof + g * (16 * 144) + j * 32);
#pragma unroll
                for (int t = 0; t < 2; t++) {
                    const int nt = 2 * g + t;
                    mma16(sacc[nt], qfh[j], &kl[2 * t]);
                    mma16(sacc[nt], qfl[j], &kb[2 * t]);
                    mma16(sacc[nt], qfh[j], &kb[2 * t]);
                }
            }

        // ---- online softmax (rows qr / qr+8 of this warp's 16-row block) ----
        float tm0 = -1e30f, tm1 = -1e30f;
#pragma unroll
        for (int nt = 0; nt < 8; nt++) {
            tm0 = fmaxf(tm0, fmaxf(sacc[nt][0], sacc[nt][1]));
            tm1 = fmaxf(tm1, fmaxf(sacc[nt][2], sacc[nt][3]));
        }
        tm0 = fmaxf(tm0, __shfl_xor_sync(0xffffffff, tm0, 1));
        tm0 = fmaxf(tm0, __shfl_xor_sync(0xffffffff, tm0, 2));
        tm1 = fmaxf(tm1, __shfl_xor_sync(0xffffffff, tm1, 1));
        tm1 = fmaxf(tm1, __shfl_xor_sync(0xffffffff, tm1, 2));
        const float mn0 = fmaxf(m0r, tm0 * 0.125f);
        const float mn1 = fmaxf(m1r, tm1 * 0.125f);
        const float f0 = exp2f((m0r - mn0) * LOG2E);
        const float f1 = exp2f((m1r - mn1) * LOG2E);
        m0r = mn0; m1r = mn1;
        const float mm0 = mn0 * LOG2E, mm1 = mn1 * LOG2E;
        float s0 = 0.0f, s1 = 0.0f;
        const int pr0 = (w * 16 + qr) * 36 + kp;
        const int pr1 = pr0 + 8 * 36;
#pragma unroll
        for (int nt = 0; nt < 8; nt++) {
            const float p0 = exp2f(fmaf(sacc[nt][0], SEXP, -mm0));
            const float p1 = exp2f(fmaf(sacc[nt][1], SEXP, -mm0));
            const float p2 = exp2f(fmaf(sacc[nt][2], SEXP, -mm1));
            const float p3 = exp2f(fmaf(sacc[nt][3], SEXP, -mm1));
            s0 += p0 + p1; s1 += p2 + p3;
            uint32_t hh, ll;
            split2(p0, p1, hh, ll);
            dsm[13824 + pr0 + nt * 4] = hh;
            dsm[18432 + pr0 + nt * 4] = ll;
            split2(p2, p3, hh, ll);
            dsm[13824 + pr1 + nt * 4] = hh;
            dsm[18432 + pr1 + nt * 4] = ll;
        }
        s0 += __shfl_xor_sync(0xffffffff, s0, 1);
        s0 += __shfl_xor_sync(0xffffffff, s0, 2);
        s1 += __shfl_xor_sync(0xffffffff, s1, 1);
        s1 += __shfl_xor_sync(0xffffffff, s1, 2);
        l0 = l0 * f0 + s0;
        l1 = l1 * f1 + s1;
#pragma unroll
        for (int nt = 0; nt < 8; nt++) {
            O[nt][0] *= f0; O[nt][1] *= f0;
            O[nt][2] *= f1; O[nt][3] *= f1;
        }
        __syncthreads();                           // sync B: P + V visible

        // ---- O += P V ----
#pragma unroll
        for (int j = 0; j < 4; j++) {
            uint32_t pah[4], pal[4];
            ldm4(pah, aof + 13824 * 4 + j * 32);
            ldm4(pal, aof + 18432 * 4 + j * 32);
#pragma unroll
            for (int g = 0; g < 4; g++) {
                uint32_t vbh[4], vbl[4];
                ldm4(vbh, smb + 9216 * 4 + bof + g * (16 * 144) + j * 32);
                ldm4(vbl, smb + 11520 * 4 + bof + g * (16 * 144) + j * 32);
#pragma unroll
                for (int t = 0; t < 2; t++) {
                    const int nt = 2 * g + t;
                    mma16(O[nt], pah, &vbl[2 * t]);
                    mma16(O[nt], pal, &vbh[2 * t]);
                    mma16(O[nt], pah, &vbh[2 * t]);
                }
            }
        }
    }

    // ---- epilogue: O /= l, write attention-out planes ----
    const float il0 = 1.0f / l0, il1 = 1.0f / l1;
    const size_t r0g = (size_t)(tokb + m0 + w * 16 + qr) * CCP + hq + kp;
    const size_t r1g = r0g + (size_t)8 * CCP;
#pragma unroll
    for (int nt = 0; nt < 8; nt++) {
        uint32_t hh, ll;
        split2(O[nt][0] * il0, O[nt][1] * il0, hh, ll);
        aoh[r0g + nt * 4] = hh; aol[r0g + nt * 4] = ll;
        split2(O[nt][2] * il1, O[nt][3] * il1, hh, ll);
        aoh[r1g + nt * 4] = hh; aol[r1g + nt * 4] = ll;
    }
}

// ---------------- unified tensor-core GEMM (bf16x3, cp.async 4-stage) ---------
// out[m,n] = sum_k A[m,k] * B[n,k]   (planes pre-split, pairs packed along k).
// Tile: 128(M) x 64(N) x 16(K), 8 warps (4x2), warp tile 32x32.
// MODE: 0 +bias | 1 gelu(+bias) | 2 +bias+add1 | 3 +bias+add1-add2
template<int MODE, bool OUTP>
__global__ void __launch_bounds__(256) mma_gemm(
    const uint32_t* __restrict__ Agh, const uint32_t* __restrict__ Agl,
    const uint32_t* __restrict__ Bgh, const uint32_t* __restrict__ Bgl,
    const float* __restrict__ bias,
    float* __restrict__ outF, uint32_t* __restrict__ outH, uint32_t* __restrict__ outL,
    int K, int ldaP, int ldbP, int ldc,
    const float* __restrict__ add1, const float* __restrict__ add2)
{
    extern __shared__ __align__(16) uint32_t dsm[];
    constexpr uint32_t STB     = 18432;      // bytes/stage
    constexpr uint32_t OFF_AL  = 6144;
    constexpr uint32_t OFF_BH  = 12288;
    constexpr uint32_t OFF_BL  = 15360;

    const int tid  = threadIdx.x;
    const int lane = tid & 31;
    const int wid  = tid >> 5;
    const int wm   = wid >> 1;
    const int wn   = wid & 1;
    const int m0   = blockIdx.y * 128;
    const int n0   = blockIdx.x * 64;

    const int nsteps = K >> 4;

    const int arow = tid >> 1;
    const int akq  = (tid & 1) << 2;

    const uint32_t smb = smem_u32(dsm);
    const uint32_t aoff = (uint32_t)(wm * 32 + (lane & 15)) * 48 + (uint32_t)(lane >> 4) * 16;
    const uint32_t boff = (uint32_t)(wn * 32 + ((lane >> 4) & 1) * 8 + (lane & 7)) * 48 +
                          (uint32_t)((lane >> 3) & 1) * 16;

    auto issue = [&](int s) {
        const uint32_t stb = smb + (uint32_t)(s & 3) * STB;
        const size_t aog = (size_t)(m0 + arow) * ldaP + (s << 3) + akq;
        const uint32_t adst = stb + (uint32_t)arow * 48 + (uint32_t)akq * 4;
        cp16(adst, Agh + aog);
        cp16(adst + OFF_AL, Agl + aog);
        if (tid < 128) {
            const int br = tid >> 1;
            const size_t bog = (size_t)(n0 + br) * ldbP + (s << 3) + akq;
            const uint32_t bdst = stb + OFF_BH + (uint32_t)br * 48 + (uint32_t)akq * 4;
            cp16(bdst, Bgh + bog);
            cp16(bdst + (OFF_BL - OFF_BH), Bgl + bog);
        }
    };

#pragma unroll
    for (int s = 0; s < 3; s++) {
        if (s < nsteps) issue(s);
        CP_COMMIT();
    }

    float acc[2][4][4];
#pragma unroll
    for (int i = 0; i < 2; i++)
#pragma unroll
        for (int j = 0; j < 4; j++)
#pragma unroll
            for (int e = 0; e < 4; e++) acc[i][j][e] = 0.0f;

    const int kp = lane & 3;
    const int qr = lane >> 2;

    for (int s = 0; s < nsteps; s++) {
        CP_WAIT2();
        __syncthreads();
        if (s + 3 < nsteps) issue(s + 3);
        CP_COMMIT();

        const uint32_t stb = smb + (uint32_t)(s & 3) * STB;
        uint32_t ah[2][4], al4[2][4];
#pragma unroll
        for (int mt = 0; mt < 2; mt++) {
            const uint32_t ao = aoff + (uint32_t)mt * 768;
            ldm4(ah[mt],  stb + ao);
            ldm4(al4[mt], stb + OFF_AL + ao);
        }
        uint32_t bfh[2][4], bfl[2][4];
#pragma unroll
        for (int ntp = 0; ntp < 2; ntp++) {
            const uint32_t bo = boff + (uint32_t)ntp * 768;
            ldm4(bfh[ntp], stb + OFF_BH + bo);
            ldm4(bfl[ntp], stb + OFF_BL + bo);
        }
#pragma unroll
        for (int mt = 0; mt < 2; mt++)
#pragma unroll
            for (int ntp = 0; ntp < 2; ntp++)
#pragma unroll
                for (int j = 0; j < 2; j++) {
                    const int nt = 2 * ntp + j;
                    mma16(acc[mt][nt], ah[mt],  &bfl[ntp][2 * j]);
                    mma16(acc[mt][nt], al4[mt], &bfh[ntp][2 * j]);
                    mma16(acc[mt][nt], ah[mt],  &bfh[ntp][2 * j]);
                }
    }

#pragma unroll
    for (int mt = 0; mt < 2; mt++) {
#pragma unroll
        for (int nt = 0; nt < 4; nt++) {
            const int r = m0 + wm * 32 + mt * 16 + qr;
            const int c = n0 + wn * 32 + nt * 8 + 2 * kp;
            float vv[4];
#pragma unroll
            for (int e = 0; e < 4; e++) {
                const int cc = c + (e & 1);
                float v = acc[mt][nt][e];
                v += bias[cc];
                if (MODE == 1) v = 0.5f * v * (1.0f + erff(v * 0.70710678118654752f));
                vv[e] = v;
            }
            if (OUTP) {
                const int cp = c >> 1;
                uint32_t h0, l0, h1, l1;
                split2(vv[0], vv[1], h0, l0);
                split2(vv[2], vv[3], h1, l1);
                outH[(size_t)r * ldc + cp] = h0;
                outL[(size_t)r * ldc + cp] = l0;
                outH[(size_t)(r + 8) * ldc + cp] = h1;
                outL[(size_t)(r + 8) * ldc + cp] = l1;
            } else {
#pragma unroll
                for (int e = 0; e < 4; e++) {
                    const int rr = r + (e >> 1) * 8;
                    const int cc = c + (e & 1);
                    const size_t oidx = (size_t)rr * ldc + cc;
                    float v = vv[e];
                    if (MODE == 2) v += add1[oidx];
                    if (MODE == 3) v += add1[oidx] - add2[oidx];
                    outF[oidx] = v;
                }
            }
        }
    }
}

// ---------------- fused add + LayerNorm -> hi/lo planes -----------------------
__global__ void ln_kernel(const float* __restrict__ zin,
                          const float* __restrict__ u,
                          const float* __restrict__ emb,
                          const float* __restrict__ w,
                          const float* __restrict__ b,
                          uint32_t* __restrict__ oh,
                          uint32_t* __restrict__ ol) {
    __shared__ float red[256];
    const int row = blockIdx.x;
    const int tid = threadIdx.x;
    const size_t base = (size_t)row * CC;
    const float2* z2 = (const float2*)(zin + base);
    const float2* u2 = u ? (const float2*)(u + base) : nullptr;
    const float2* e2 = emb ? (const float2*)emb : nullptr;

    float2 va = z2[tid];
    float2 vb = make_float2(0.f, 0.f);
    if (u2) { float2 t = u2[tid]; va.x += t.x; va.y += t.y; }
    if (e2) { float2 t = e2[tid]; va.x += 0.1f * t.x; va.y += 0.1f * t.y; }
    if (tid < 128) {
        vb = z2[256 + tid];
        if (u2) { float2 t = u2[256 + tid]; vb.x += t.x; vb.y += t.y; }
        if (e2) { float2 t = e2[256 + tid]; vb.x += 0.1f * t.x; vb.y += 0.1f * t.y; }
    }
    float s = va.x + va.y + vb.x + vb.y;
    red[tid] = s; __syncthreads();
    for (int st = 128; st > 0; st >>= 1) {
        if (tid < st) red[tid] += red[tid + st];
        __syncthreads();
    }
    const float mu = red[0] * (1.0f / CC);
    __syncthreads();
    va.x -= mu; va.y -= mu;
    float s2 = va.x * va.x + va.y * va.y;
    if (tid < 128) { vb.x -= mu; vb.y -= mu; s2 += vb.x * vb.x + vb.y * vb.y; }
    red[tid] = s2; __syncthreads();
    for (int st = 128; st > 0; st >>= 1) {
        if (tid < st) red[tid] += red[tid + st];
        __syncthreads();
    }
    const float rs = rsqrtf(red[0] * (1.0f / CC) + 1e-5f);

    const float2* w2 = (const float2*)w;
    const float2* b2 = (const float2*)b;
    {
        float2 wc = w2[tid], bc = b2[tid];
        float y0 = va.x * rs * wc.x + bc.x;
        float y1 = va.y * rs * wc.y + bc.y;
        uint32_t hv, lv;
        split2(y0, y1, hv, lv);
        oh[(size_t)row * CCP + tid] = hv;
        ol[(size_t)row * CCP + tid] = lv;
    }
    if (tid < 128) {
        float2 wc = w2[256 + tid], bc = b2[256 + tid];
        float y0 = vb.x * rs * wc.x + bc.x;
        float y1 = vb.y * rs * wc.y + bc.y;
        uint32_t hv, lv;
        split2(y0, y1, hv, lv);
        oh[(size_t)row * CCP + 256 + tid] = hv;
        ol[(size_t)row * CCP + 256 + tid] = lv;
    }
}

// ---------------- Anderson acceleration update (one block per token) ---------
__global__ void anderson_kernel(float* __restrict__ z,
                                const float* __restrict__ res,
                                float* __restrict__ fh, int it) {
    __shared__ float sh[14][256];
    __shared__ float alpha_sh[4];
    const int n = blockIdx.x, tid = threadIdx.x;
    const size_t base = (size_t)n * CC;
    const int K = it < 4 ? it : 4;
    const int c0 = tid, c1 = tid + 256, c2 = tid + 512;

    float r0 = res[base + c0], r1 = res[base + c1], r2 = res[base + c2];
    float dF[4][3];
    for (int j = 0; j < K; j++) {
        const int slot = (it - K + j) & 3;
        const float* f = fh + (size_t)slot * ZSZ + base;
        dF[j][0] = f[c0] - r0; dF[j][1] = f[c1] - r1; dF[j][2] = f[c2] - r2;
    }

    if (K > 0) {
        int idx = 0;
        for (int k = 0; k < K; k++)
            for (int l = k; l < K; l++) {
                sh[idx][tid] = dF[k][0] * dF[l][0] + dF[k][1] * dF[l][1] + dF[k][2] * dF[l][2];
                idx++;
            }
        for (int k = 0; k < K; k++) {
            sh[idx][tid] = dF[k][0] * r0 + dF[k][1] * r1 + dF[k][2] * r2;
            idx++;
        }
        const int np = idx;
        __syncthreads();
        for (int st = 128; st > 0; st >>= 1) {
            if (tid < st)
                for (int v = 0; v < np; v++) sh[v][tid] += sh[v][tid + st];
            __syncthreads();
        }
        if (tid == 0) {
            float G[4][4], bv[4], al[4];
            int id2 = 0;
            for (int k = 0; k < K; k++)
                for (int l = k; l < K; l++) { G[k][l] = G[l][k] = sh[id2][0]; id2++; }
            for (int k = 0; k < K; k++) { G[k][k] += 1e-6f; bv[k] = sh[id2][0]; id2++; }
            for (int p = 0; p < K; p++) {
                const float inv = 1.0f / G[p][p];
                for (int rr = p + 1; rr < K; rr++) {
                    const float f2 = G[rr][p] * inv;
                    for (int cc = p; cc < K; cc++) G[rr][cc] -= f2 * G[p][cc];
                    bv[rr] -= f2 * bv[p];
                }
            }
            for (int p = K - 1; p >= 0; p--) {
                float s = bv[p];
                for (int cc = p + 1; cc < K; cc++) s -= G[p][cc] * al[cc];
                al[p] = s / G[p][p];
            }
            for (int k = 0; k < K; k++) alpha_sh[k] = al[k];
        }
        __syncthreads();
        float d0 = r0, d1 = r1, d2 = r2;
        for (int j = 0; j < K; j++) {
            const float a = alpha_sh[j];
            d0 -= a * dF[j][0]; d1 -= a * dF[j][1]; d2 -= a * dF[j][2];
        }
        z[base + c0] += d0; z[base + c1] += d1; z[base + c2] += d2;
    } else {
        z[base + c0] += r0; z[base + c1] += r1; z[base + c2] += r2;
    }

    float* fs = fh + (size_t)(it & 3) * ZSZ + base;
    fs[c0] = r0; fs[c1] = r1; fs[c2] = r2;
}

// ---------------- host launcher ----------------------------------------------
template <typename T>
static T* symaddr(const void* s) {
    void* p = nullptr;
    cudaGetSymbolAddress(&p, s);
    return (T*)p;
}

#define GEMM_SMEM  73728
#define FLASH_SMEM 92160

extern "C" void kernel_launch(void* const* d_in, const int* in_sizes, int n_in,
                              void* d_out, int out_size) {
    const float* u          = (const float*)d_in[0];
    const float* iter_emb   = (const float*)d_in[1];
    const float* ln1_w      = (const float*)d_in[2];
    const float* ln1_b      = (const float*)d_in[3];
    const float* in_proj_w  = (const float*)d_in[4];
    const float* in_proj_b  = (const float*)d_in[5];
    const float* out_proj_w = (const float*)d_in[6];
    const float* out_proj_b = (const float*)d_in[7];
    const float* ln2_w      = (const float*)d_in[8];
    const float* ln2_b      = (const float*)d_in[9];
    const float* mlp_w1     = (const float*)d_in[10];
    const float* mlp_b1     = (const float*)d_in[11];
    const float* mlp_w2     = (const float*)d_in[12];
    const float* mlp_b2     = (const float*)d_in[13];
    // d_in[14] = num_iters (fixed to 6 by setup_inputs)

    float* zp   = symaddr<float>(g_z);
    float* zap  = symaddr<float>(g_zattn);
    float* resp = symaddr<float>(g_res);
    float* fhp  = symaddr<float>(g_fhist);
    uint32_t* xh   = symaddr<uint32_t>(g_x_h);    uint32_t* xl   = symaddr<uint32_t>(g_x_l);
    uint32_t* qh   = symaddr<uint32_t>(g_qkv_h);  uint32_t* ql   = symaddr<uint32_t>(g_qkv_l);
    uint32_t* aoh  = symaddr<uint32_t>(g_ao_h);   uint32_t* aol  = symaddr<uint32_t>(g_ao_l);
    uint32_t* mih  = symaddr<uint32_t>(g_mid_h);  uint32_t* mil  = symaddr<uint32_t>(g_mid_l);
    uint32_t* wqh  = symaddr<uint32_t>(g_wqkv_h); uint32_t* wql  = symaddr<uint32_t>(g_wqkv_l);
    uint32_t* woh  = symaddr<uint32_t>(g_wo_h);   uint32_t* wol  = symaddr<uint32_t>(g_wo_l);
    uint32_t* w1h  = symaddr<uint32_t>(g_w1_h);   uint32_t* w1l  = symaddr<uint32_t>(g_w1_l);
    uint32_t* w2h  = symaddr<uint32_t>(g_w2_h);   uint32_t* w2l  = symaddr<uint32_t>(g_w2_l);

    cudaFuncSetAttribute((const void*)mma_gemm<0, true>,  cudaFuncAttributeMaxDynamicSharedMemorySize, GEMM_SMEM);
    cudaFuncSetAttribute((const void*)mma_gemm<2, false>, cudaFuncAttributeMaxDynamicSharedMemorySize, GEMM_SMEM);
    cudaFuncSetAttribute((const void*)mma_gemm<1, true>,  cudaFuncAttributeMaxDynamicSharedMemorySize, GEMM_SMEM);
    cudaFuncSetAttribute((const void*)mma_gemm<3, false>, cudaFuncAttributeMaxDynamicSharedMemorySize, GEMM_SMEM);
    cudaFuncSetAttribute((const void*)flash_attn,         cudaFuncAttributeMaxDynamicSharedMemorySize, FLASH_SMEM);

    cudaMemsetAsync(zp, 0, (size_t)ZSZ * sizeof(float), 0);

    // split weights once per launch
    conv_kernel<<<(C3 * CCP + 255) / 256, 256>>>(in_proj_w,  wqh, wql, C3 * CCP);
    conv_kernel<<<(CC * CCP + 255) / 256, 256>>>(out_proj_w, woh, wol, CC * CCP);
    conv_kernel<<<(C4 * CCP + 255) / 256, 256>>>(mlp_w1,     w1h, w1l, C4 * CCP);
    conv_kernel<<<(CC * C4P + 255) / 256, 256>>>(mlp_w2,     w2h, w2l, CC * C4P);

    for (int it = 0; it < NUM_ITERS; it++) {
        // x = LN1(z + 0.1*emb[it] + u) -> planes
        ln_kernel<<<BT, 256>>>(zp, u, iter_emb + it * CC, ln1_w, ln1_b, xh, xl);

        // qkv = x @ Wqkv^T + b  -> planes
        mma_gemm<0, true><<<dim3(C3 / 64, BT / 128), 256, GEMM_SMEM>>>(
            xh, xl, wqh, wql, in_proj_b, nullptr, qh, ql,
            CC, CCP, CCP, C3P, nullptr, nullptr);

        // fused attention: softmax(QK^T/8) @ V  -> planes
        flash_attn<<<dim3(TT / 128, BB * HH), 256, FLASH_SMEM>>>(qh, ql, aoh, aol);

        // z_attn = z + attnout @ Wo^T + bo  (fp32)
        mma_gemm<2, false><<<dim3(CC / 64, BT / 128), 256, GEMM_SMEM>>>(
            aoh, aol, woh, wol, out_proj_b, zap, nullptr, nullptr,
            CC, CCP, CCP, CC, zp, nullptr);

        // h = LN2(z_attn) -> planes
        ln_kernel<<<BT, 256>>>(zap, nullptr, nullptr, ln2_w, ln2_b, xh, xl);

        // mid = gelu(h @ W1^T + b1) -> planes
        mma_gemm<1, true><<<dim3(C4 / 64, BT / 128), 256, GEMM_SMEM>>>(
            xh, xl, w1h, w1l, mlp_b1, nullptr, mih, mil,
            CC, CCP, CCP, C4P, nullptr, nullptr);

        // res = (mid @ W2^T + b2) + z_attn - z  (fp32)
        mma_gemm<3, false><<<dim3(CC / 64, BT / 128), 256, GEMM_SMEM>>>(
            mih, mil, w2h, w2l, mlp_b2, resp, nullptr, nullptr,
            C4, C4P, C4P, CC, zap, zp);

        // Anderson update of z, residual history push
        anderson_kernel<<<BT, 256>>>(zp, resp, fhp, it);
    }

    cudaMemcpyAsync(d_out, zp, (size_t)ZSZ * sizeof(float),
                    cudaMemcpyDeviceToDevice, 0);
}